// round 13
// baseline (speedup 1.0000x reference)
#include <cuda_runtime.h>
#include <cuda_bf16.h>
#include <math.h>
#include <stdint.h>

#define NWIN 64
#define NTOK 512
#define NHEAD 8
#define HDIM 32
#define CDIM 256
#define KCAT2 512           // [hi(256) | lo(256)]
#define MTOT 32768

#define LOG2E 1.4426950408889634f
#define QSCALE (0.17677669529663687f * 1.4426950408889634f)

__device__ __nv_bfloat16 g_qh[(size_t)512 * 512 * 32];
__device__ __nv_bfloat16 g_ql[(size_t)512 * 512 * 32];
__device__ __nv_bfloat16 g_kh[(size_t)512 * 512 * 32];
__device__ __nv_bfloat16 g_kl[(size_t)512 * 512 * 32];
__device__ __nv_bfloat16 g_vth[(size_t)512 * 32 * 512];
__device__ __nv_bfloat16 g_vtl[(size_t)512 * 32 * 512];
__device__ __nv_bfloat16 g_bfrag[(size_t)8 * 8 * 32 * 64 * 128];
__device__ int   g_tokoff[NWIN * NTOK];
__device__ __nv_bfloat16 g_acat[(size_t)MTOT * KCAT2];
__device__ __nv_bfloat16 g_bcat[(size_t)768 * KCAT2];

__device__ __forceinline__ uint32_t smem_u32(const void* p) {
    uint32_t a;
    asm("{ .reg .u64 t; cvta.to.shared.u64 t, %1; cvt.u32.u64 %0, t; }" : "=r"(a) : "l"(p));
    return a;
}
__device__ __forceinline__ void ldmx4(uint32_t* r, uint32_t addr) {
    asm volatile("ldmatrix.sync.aligned.m8n8.x4.shared.b16 {%0,%1,%2,%3}, [%4];"
                 : "=r"(r[0]), "=r"(r[1]), "=r"(r[2]), "=r"(r[3]) : "r"(addr));
}
__device__ __forceinline__ void st128(uint32_t addr, uint4 v) {
    asm volatile("st.shared.v4.b32 [%0], {%1,%2,%3,%4};"
                 :: "r"(addr), "r"(v.x), "r"(v.y), "r"(v.z), "r"(v.w) : "memory");
}
__device__ __forceinline__ void mma16816(float* c, const uint32_t* a, const uint32_t* b) {
    asm volatile("mma.sync.aligned.m16n8k16.row.col.f32.bf16.bf16.f32 "
                 "{%0,%1,%2,%3}, {%4,%5,%6,%7}, {%8,%9}, {%0,%1,%2,%3};"
                 : "+f"(c[0]), "+f"(c[1]), "+f"(c[2]), "+f"(c[3])
                 : "r"(a[0]), "r"(a[1]), "r"(a[2]), "r"(a[3]), "r"(b[0]), "r"(b[1]));
}
__device__ __forceinline__ void split2(float f0, float f1, uint32_t& hi, uint32_t& lo) {
    __nv_bfloat16 h0 = __float2bfloat16(f0), h1 = __float2bfloat16(f1);
    __nv_bfloat16 l0 = __float2bfloat16(f0 - __bfloat162float(h0));
    __nv_bfloat16 l1 = __float2bfloat16(f1 - __bfloat162float(h1));
    uint16_t uh0 = *(uint16_t*)&h0, uh1 = *(uint16_t*)&h1;
    uint16_t ul0 = *(uint16_t*)&l0, ul1 = *(uint16_t*)&l1;
    hi = (uint32_t)uh0 | ((uint32_t)uh1 << 16);
    lo = (uint32_t)ul0 | ((uint32_t)ul1 << 16);
}
#define CPA16(dst, src) \
    asm volatile("cp.async.cg.shared.global [%0], [%1], 16;" :: "r"(dst), "l"(src) : "memory")
#define CPC() asm volatile("cp.async.commit_group;" ::: "memory")
#define CPW0() asm volatile("cp.async.wait_group 0;" ::: "memory")

// ---------------------------------------------------------------------------
__global__ void prep_tok_kernel() {
    int gid = blockIdx.x * 256 + threadIdx.x;
    int w = gid >> 9, n = gid & 511;
    int wh = w >> 4, ww = (w >> 2) & 3, wd = w & 3;
    int ih = n >> 6, iw = (n >> 3) & 7, id = n & 7;
    int gh = (wh * 8 + ih + 4) & 31;
    int gw = (ww * 8 + iw + 4) & 31;
    int gd = (wd * 8 + id + 4) & 31;
    g_tokoff[gid] = ((gh * 32 + gw) * 32 + gd) * 256;
}

// ---------------------------------------------------------------------------
__global__ void __launch_bounds__(512) prep_bias_kernel(const float* __restrict__ rpb) {
    int cfg = blockIdx.x >> 9, i = blockIdx.x & 511;
    int h = threadIdx.x >> 6, jb = threadIdx.x & 63;
    int ch = (cfg >> 2) & 1, cw = (cfg >> 1) & 1, cd = cfg & 1;
    int i0 = i >> 6, i1 = (i >> 3) & 7, i2 = i & 7;
    int ri = (ch ? (i0 < 4 ? 1 : 2) : 0) * 9 + (cw ? (i1 < 4 ? 1 : 2) : 0) * 3
           + (cd ? (i2 < 4 ? 1 : 2) : 0);
    int ib = i >> 4, half = (i & 15) >> 3, row = i & 7;
    int j0 = jb >> 3, j1 = jb & 7;
    int rjb = (ch ? (j0 < 4 ? 1 : 2) : 0) * 9 + (cw ? (j1 < 4 ? 1 : 2) : 0) * 3;
    int idxb = (i0 - j0 + 7) * 225 + (i1 - j1 + 7) * 15;
    union { __nv_bfloat16 h8[8]; uint4 u; } O;
#pragma unroll
    for (int j2 = 0; j2 < 8; j2++) {
        int rj = rjb + (cd ? (j2 < 4 ? 1 : 2) : 0);
        int idx = idxb + (i2 - j2 + 7);
        float m = (ri == rj) ? 0.f : -100.f;
        O.h8[j2] = __float2bfloat16((rpb[idx * 8 + h] + m) * LOG2E);
    }
    size_t base = (((((size_t)cfg * 8 + h) * 32 + ib) * 64 + jb) * 128) + half * 64 + row * 8;
    *(uint4*)(g_bfrag + base) = O.u;
}

// ---------------------------------------------------------------------------
__global__ void conv_a_kernel(const float* __restrict__ src) {
    int row = blockIdx.x * 8 + (threadIdx.x >> 5);
    int c8 = (threadIdx.x & 31) * 8;
    const float* sp = src + g_tokoff[row];
    float4 v0 = *(const float4*)(sp + c8);
    float4 v1 = *(const float4*)(sp + c8 + 4);
    float f[8] = {v0.x, v0.y, v0.z, v0.w, v1.x, v1.y, v1.z, v1.w};
    union { __nv_bfloat16 h[8]; uint4 u; } H, L;
#pragma unroll
    for (int i = 0; i < 8; i++) {
        H.h[i] = __float2bfloat16(f[i]);
        L.h[i] = __float2bfloat16(f[i] - __bfloat162float(H.h[i]));
    }
    __nv_bfloat16* dst = g_acat + (size_t)row * KCAT2;
    *(uint4*)(dst + c8)       = H.u;
    *(uint4*)(dst + 256 + c8) = L.u;
}

__global__ void conv_w_kernel(const float* __restrict__ W) {
    int row = blockIdx.x;
    int c8 = threadIdx.x * 8;
    const float* sp = W + (size_t)row * 256 + c8;
    float4 v0 = *(const float4*)(sp);
    float4 v1 = *(const float4*)(sp + 4);
    float f[8] = {v0.x, v0.y, v0.z, v0.w, v1.x, v1.y, v1.z, v1.w};
    union { __nv_bfloat16 h[8]; uint4 u; } H, L;
#pragma unroll
    for (int i = 0; i < 8; i++) {
        H.h[i] = __float2bfloat16(f[i]);
        L.h[i] = __float2bfloat16(f[i] - __bfloat162float(H.h[i]));
    }
    __nv_bfloat16* dst = g_bcat + (size_t)row * KCAT2;
    *(uint4*)(dst + c8)       = H.u;
    *(uint4*)(dst + 256 + c8) = L.u;
}

// ---------------------------------------------------------------------------
// HMMA GEMM (unchanged from R12 superchunk form).
// ---------------------------------------------------------------------------
__global__ void __launch_bounds__(256, 2) hmma_gemm_kernel(const float* __restrict__ bias,
                                                           float* __restrict__ out, int mode) {
    extern __shared__ __align__(16) char smem[];
    uint32_t sbase = smem_u32(smem);
    int tid = threadIdx.x;
    int lane = tid & 31, wid = tid >> 5;
    int wm = wid & 3, wn = wid >> 2;
    int m0 = blockIdx.x * 128, n0 = blockIdx.y * 128;

    int lr = tid >> 1, lh = tid & 1;
    const char* Arow = (const char*)g_acat + (size_t)(m0 + lr) * 1024;
    const char* Brow = (const char*)g_bcat + (size_t)(n0 + lr) * 1024;
    uint32_t stoff = (uint32_t)(lr * 80 + lh * 32);

    const uint32_t AH = 0, AL = 10240, BH = 20480, BL = 30720;

    auto issue = [&](int n) {
        uint32_t st = sbase + (uint32_t)(n & 1) * 40960u;
        int so = n * 64 + lh * 32;
#pragma unroll
        for (int i = 0; i < 2; i++) {
            CPA16(st + AH + stoff + i * 16, Arow + so + i * 16);
            CPA16(st + AL + stoff + i * 16, Arow + 512 + so + i * 16);
            CPA16(st + BH + stoff + i * 16, Brow + so + i * 16);
            CPA16(st + BL + stoff + i * 16, Brow + 512 + so + i * 16);
        }
        CPC();
    };

    uint32_t aoff = (uint32_t)((((lane & 7) + ((lane >> 3) & 1) * 8) * 80) + (lane >> 4) * 16);
    uint32_t boff = (uint32_t)((((lane & 7) + (lane >> 4) * 8) * 80) + ((lane >> 3) & 1) * 16);

    float acc[2][8][4];
#pragma unroll
    for (int a = 0; a < 2; a++)
#pragma unroll
        for (int b = 0; b < 8; b++)
#pragma unroll
            for (int c = 0; c < 4; c++) acc[a][b][c] = 0.f;

    issue(0);
    CPW0();
    __syncthreads();

#pragma unroll 1
    for (int c = 0; c < 8; c++) {
        if (c < 7) issue(c + 1);

        uint32_t st = sbase + (uint32_t)(c & 1) * 40960u;
        uint32_t AHw = st + AH + (uint32_t)(wm * 32) * 80u + aoff;
        uint32_t ALw = st + AL + (uint32_t)(wm * 32) * 80u + aoff;
        uint32_t BHw = st + BH + (uint32_t)(wn * 64) * 80u + boff;
        uint32_t BLw = st + BL + (uint32_t)(wn * 64) * 80u + boff;
#pragma unroll
        for (int ks = 0; ks < 2; ks++) {
            uint32_t ah[2][4], al[2][4];
#pragma unroll
            for (int mt = 0; mt < 2; mt++) {
                ldmx4(ah[mt], AHw + (uint32_t)(mt * 16) * 80u + ks * 32u);
                ldmx4(al[mt], ALw + (uint32_t)(mt * 16) * 80u + ks * 32u);
            }
            uint32_t bh[8][2];
#pragma unroll
            for (int p = 0; p < 4; p++) {
                uint32_t t4[4];
                ldmx4(t4, BHw + (uint32_t)(p * 16) * 80u + ks * 32u);
                bh[2 * p][0] = t4[0]; bh[2 * p][1] = t4[1];
                bh[2 * p + 1][0] = t4[2]; bh[2 * p + 1][1] = t4[3];
            }
#pragma unroll
            for (int mt = 0; mt < 2; mt++)
#pragma unroll
                for (int nt = 0; nt < 8; nt++) {
                    mma16816(acc[mt][nt], ah[mt], bh[nt]);
                    mma16816(acc[mt][nt], al[mt], bh[nt]);
                }
            uint32_t bl[8][2];
#pragma unroll
            for (int p = 0; p < 4; p++) {
                uint32_t t4[4];
                ldmx4(t4, BLw + (uint32_t)(p * 16) * 80u + ks * 32u);
                bl[2 * p][0] = t4[0]; bl[2 * p][1] = t4[1];
                bl[2 * p + 1][0] = t4[2]; bl[2 * p + 1][1] = t4[3];
            }
#pragma unroll
            for (int mt = 0; mt < 2; mt++)
#pragma unroll
                for (int nt = 0; nt < 8; nt++)
                    mma16816(acc[mt][nt], ah[mt], bl[nt]);
        }
        if (c < 7) {
            CPW0();
            __syncthreads();
        }
    }

    int quad = lane >> 2, tg = lane & 3;
#pragma unroll
    for (int mt = 0; mt < 2; mt++) {
        int rbase = m0 + wm * 32 + mt * 16 + quad;
#pragma unroll
        for (int nt = 0; nt < 8; nt++) {
            int col = n0 + wn * 64 + nt * 8 + tg * 2;
            float2 bb = *(const float2*)(bias + col);
            if (mode == 0) {
                int sec = n0 >> 8;
                float sc = (sec == 0) ? QSCALE : 1.0f;
                int head = (col & 255) >> 5, dd = col & 31;
#pragma unroll
                for (int hf = 0; hf < 2; hf++) {
                    int rr = rbase + hf * 8;
                    int w = rr >> 9, nn = rr & 511;
                    size_t bxi = (size_t)(w * 8 + head);
                    float f0 = (acc[mt][nt][hf * 2 + 0] + bb.x) * sc;
                    float f1 = (acc[mt][nt][hf * 2 + 1] + bb.y) * sc;
                    uint32_t hi, lo;
                    split2(f0, f1, hi, lo);
                    if (sec <= 1) {
                        __nv_bfloat16* dh = (sec == 0 ? g_qh : g_kh) + (bxi * 512 + nn) * 32 + dd;
                        __nv_bfloat16* dl = (sec == 0 ? g_ql : g_kl) + (bxi * 512 + nn) * 32 + dd;
                        *(uint32_t*)dh = hi;
                        *(uint32_t*)dl = lo;
                    } else {
                        g_vth[(bxi * 32 + dd) * 512 + nn]     = *(__nv_bfloat16*)&hi;
                        g_vth[(bxi * 32 + dd + 1) * 512 + nn] = ((__nv_bfloat162*)&hi)->y;
                        g_vtl[(bxi * 32 + dd) * 512 + nn]     = *(__nv_bfloat16*)&lo;
                        g_vtl[(bxi * 32 + dd + 1) * 512 + nn] = ((__nv_bfloat162*)&lo)->y;
                    }
                }
            } else {
#pragma unroll
                for (int hf = 0; hf < 2; hf++) {
                    int rr = rbase + hf * 8;
                    int off = g_tokoff[rr] + col;
                    float2 o;
                    o.x = acc[mt][nt][hf * 2 + 0] + bb.x;
                    o.y = acc[mt][nt][hf * 2 + 1] + bb.y;
                    *(float2*)(out + off) = o;
                }
            }
        }
    }
}

// ---------------------------------------------------------------------------
// HMMA attention, warp M-tile widened to 32 q-rows: 4 warps x 32 rows per
// 128-row CTA (block=128). Each K/V fragment now feeds 2 m-tiles -> K/V
// LDSM per unit of work halved (ratio 3 -> 6).
// smem: Qh 10240 | Ql 10240 | 2 x 19456 KV stages. Total 59392.
// ---------------------------------------------------------------------------
__global__ void __launch_bounds__(128, 2) attn_mma_kernel() {
    extern __shared__ __align__(16) char sm[];
    uint32_t sb = smem_u32(sm);
    const int tid = threadIdx.x, lane = tid & 31, wid = tid >> 5;  // wid 0..3
    int bx = blockIdx.x >> 2, mtile = blockIdx.x & 3;
    int w = bx >> 3, h = bx & 7;
    int cfg = (((w >> 4) == 3) ? 4 : 0) | ((((w >> 2) & 3) == 3) ? 2 : 0) | (((w & 3) == 3) ? 1 : 0);

    const uint32_t SQH = 0, SQL = 10240, SBUF = 20480, BSTR = 19456;
    const uint32_t KH = 0, KL = 5120, VTH = 10240, VTL = 14848;

    // K staging (128 thr): thread t -> K row t>>1 (64B), half (t&1)*32.
    int row_k = tid >> 1, segb_k = (tid & 1) * 32;
    // V staging: thread t -> V row t>>2 (128B), quarter (t&3)*32.
    int row_v = tid >> 2, segb_v = (tid & 3) * 32;
    const char* kga = (const char*)g_kh + (size_t)bx * 32768 + row_k * 64 + segb_k;
    const char* kgb = (const char*)g_kl + (size_t)bx * 32768 + row_k * 64 + segb_k;
    const char* vga = (const char*)g_vth + (size_t)bx * 32768 + row_v * 1024 + segb_v;
    const char* vgb = (const char*)g_vtl + (size_t)bx * 32768 + row_v * 1024 + segb_v;
    uint32_t kdst = row_k * 80 + segb_k;
    uint32_t vdst = row_v * 144 + segb_v;

    auto issueKV = [&](int n) {
        uint32_t B2 = sb + SBUF + (uint32_t)(n & 1) * BSTR;
#pragma unroll
        for (int i = 0; i < 2; i++) {
            CPA16(B2 + KH + kdst + i * 16, kga + (size_t)n * 4096 + i * 16);
            CPA16(B2 + KL + kdst + i * 16, kgb + (size_t)n * 4096 + i * 16);
            CPA16(B2 + VTH + vdst + i * 16, vga + (size_t)n * 128 + i * 16);
            CPA16(B2 + VTL + vdst + i * 16, vgb + (size_t)n * 128 + i * 16);
        }
        CPC();
    };

    issueKV(0);

    // stage Q (128 rows x 64B, stride 80B) with 128 threads: 4 chunks each
#pragma unroll
    for (int u = 0; u < 4; u++) {
        int lin = tid + u * 128;
        int row = lin >> 2, seg = lin & 3;
        size_t src = ((size_t)bx * 512 + mtile * 128 + row) * 32 + seg * 8;
        st128(sb + SQH + row * 80 + seg * 16, *(const uint4*)(g_qh + src));
        st128(sb + SQL + row * 80 + seg * 16, *(const uint4*)(g_ql + src));
    }
    CPW0();
    __syncthreads();

    uint32_t aoff = (uint32_t)(((lane & 7) + ((lane >> 3) & 1) * 8) * 80 + (lane >> 4) * 16);
    uint32_t boff = (uint32_t)(((lane & 7) + (lane >> 4) * 8) * 80 + ((lane >> 3) & 1) * 16);
    uint32_t vboff = (uint32_t)(((lane & 7) + (lane >> 4) * 8) * 144 + ((lane >> 3) & 1) * 16);

    // Q frags: 2 m-tiles of 16 rows each (warp covers rows wid*32 .. +32)
    uint32_t qh[2][2][4], ql[2][2][4];
#pragma unroll
    for (int mt = 0; mt < 2; mt++)
#pragma unroll
        for (int ks = 0; ks < 2; ks++) {
            uint32_t rbase = (uint32_t)(wid * 32 + mt * 16) * 80;
            ldmx4(qh[mt][ks], sb + SQH + rbase + aoff + ks * 32);
            ldmx4(ql[mt][ks], sb + SQL + rbase + aoff + ks * 32);
        }

    float oacc[2][4][4];
#pragma unroll
    for (int m = 0; m < 2; m++)
#pragma unroll
        for (int a = 0; a < 4; a++)
#pragma unroll
            for (int b = 0; b < 4; b++) oacc[m][a][b] = 0.f;
    float rs[2][2] = {{0.f, 0.f}, {0.f, 0.f}};
    int quad = lane >> 2, tg = lane & 3;
    int ib0 = mtile * 8 + wid * 2;
    const __nv_bfloat16* bf0 = g_bfrag + ((((size_t)cfg * 8 + h) * 32 + ib0) * 64) * 128;
    const __nv_bfloat16* bf1 = bf0 + (size_t)64 * 128;

#pragma unroll 1
    for (int jt = 0; jt < 8; jt++) {
        if (jt < 7) issueKV(jt + 1);
        uint32_t B = sb + SBUF + (uint32_t)(jt & 1) * BSTR;

        float sacc[2][8][4];
#pragma unroll
        for (int m = 0; m < 2; m++)
#pragma unroll
            for (int a = 0; a < 8; a++)
#pragma unroll
                for (int b = 0; b < 4; b++) sacc[m][a][b] = 0.f;
#pragma unroll
        for (int ks = 0; ks < 2; ks++)
#pragma unroll
            for (int p = 0; p < 4; p++) {
                uint32_t bh[4], bl[4];
                ldmx4(bh, B + KH + (uint32_t)(p * 16) * 80 + boff + ks * 32);
                ldmx4(bl, B + KL + (uint32_t)(p * 16) * 80 + boff + ks * 32);
#pragma unroll
                for (int mt = 0; mt < 2; mt++)
#pragma unroll
                    for (int n2 = 0; n2 < 2; n2++) {
                        mma16816(sacc[mt][2 * p + n2], qh[mt][ks], &bh[n2 * 2]);
                        mma16816(sacc[mt][2 * p + n2], qh[mt][ks], &bl[n2 * 2]);
                        mma16816(sacc[mt][2 * p + n2], ql[mt][ks], &bh[n2 * 2]);
                    }
            }

        uint32_t aPhi[2][4][4], aPlo[2][4][4];
#pragma unroll
        for (int mt = 0; mt < 2; mt++) {
            const __nv_bfloat16* bfm = (mt == 0) ? bf0 : bf1;
#pragma unroll
            for (int nt = 0; nt < 8; nt++) {
                const uint32_t* bp = (const uint32_t*)(bfm + (size_t)(jt * 8 + nt) * 128);
                __nv_bfloat162 bb01 = *(const __nv_bfloat162*)&bp[quad * 4 + tg];
                __nv_bfloat162 bb23 = *(const __nv_bfloat162*)&bp[32 + quad * 4 + tg];
                float2 b01 = __bfloat1622float2(bb01);
                float2 b23 = __bfloat1622float2(bb23);
                float p0 = exp2f(sacc[mt][nt][0] + b01.x);
                float p1 = exp2f(sacc[mt][nt][1] + b01.y);
                float p2 = exp2f(sacc[mt][nt][2] + b23.x);
                float p3 = exp2f(sacc[mt][nt][3] + b23.y);
                rs[mt][0] += p0 + p1;
                rs[mt][1] += p2 + p3;
                int kt = nt >> 1, o = (nt & 1) * 2;
                split2(p0, p1, aPhi[mt][kt][o], aPlo[mt][kt][o]);
                split2(p2, p3, aPhi[mt][kt][o + 1], aPlo[mt][kt][o + 1]);
            }
        }

#pragma unroll
        for (int kt = 0; kt < 4; kt++)
#pragma unroll
            for (int np = 0; np < 2; np++) {
                uint32_t vh[4], vl[4];
                ldmx4(vh, B + VTH + (uint32_t)(np * 16) * 144 + vboff + kt * 32);
                ldmx4(vl, B + VTL + (uint32_t)(np * 16) * 144 + vboff + kt * 32);
#pragma unroll
                for (int mt = 0; mt < 2; mt++)
#pragma unroll
                    for (int n2 = 0; n2 < 2; n2++) {
                        mma16816(oacc[mt][np * 2 + n2], aPhi[mt][kt], &vh[n2 * 2]);
                        mma16816(oacc[mt][np * 2 + n2], aPhi[mt][kt], &vl[n2 * 2]);
                        mma16816(oacc[mt][np * 2 + n2], aPlo[mt][kt], &vh[n2 * 2]);
                    }
            }

        if (jt < 7) {
            CPW0();
            __syncthreads();
        }
    }

#pragma unroll
    for (int mt = 0; mt < 2; mt++) {
        rs[mt][0] += __shfl_xor_sync(0xFFFFFFFF, rs[mt][0], 1);
        rs[mt][0] += __shfl_xor_sync(0xFFFFFFFF, rs[mt][0], 2);
        rs[mt][1] += __shfl_xor_sync(0xFFFFFFFF, rs[mt][1], 1);
        rs[mt][1] += __shfl_xor_sync(0xFFFFFFFF, rs[mt][1], 2);
        float inv0 = 1.f / rs[mt][0], inv1 = 1.f / rs[mt][1];
        int qtok = mtile * 128 + wid * 32 + mt * 16 + quad;
        int t0 = w * 512 + qtok, t1 = t0 + 8;
#pragma unroll
        for (int nt = 0; nt < 4; nt++) {
            int c = h * 32 + nt * 8 + tg * 2;
            uint32_t hi, lo;
            split2(oacc[mt][nt][0] * inv0, oacc[mt][nt][1] * inv0, hi, lo);
            __nv_bfloat16* d0 = g_acat + (size_t)t0 * KCAT2 + c;
            *(uint32_t*)d0         = hi;
            *(uint32_t*)(d0 + 256) = lo;
            split2(oacc[mt][nt][2] * inv1, oacc[mt][nt][3] * inv1, hi, lo);
            __nv_bfloat16* d1 = g_acat + (size_t)t1 * KCAT2 + c;
            *(uint32_t*)d1         = hi;
            *(uint32_t*)(d1 + 256) = lo;
        }
    }
}

extern "C" void kernel_launch(void* const* d_in, const int* in_sizes, int n_in,
                              void* d_out, int out_size) {
    const float* x      = (const float*)d_in[0];
    const float* qkv_w  = (const float*)d_in[1];
    const float* qkv_b  = (const float*)d_in[2];
    const float* proj_w = (const float*)d_in[3];
    const float* proj_b = (const float*)d_in[4];
    const float* rpb    = (const float*)d_in[5];
    float* out = (float*)d_out;

    cudaFuncSetAttribute(hmma_gemm_kernel, cudaFuncAttributeMaxDynamicSharedMemorySize, 81920);
    cudaFuncSetAttribute(attn_mma_kernel, cudaFuncAttributeMaxDynamicSharedMemorySize, 59392);

    prep_tok_kernel<<<128, 256>>>();
    prep_bias_kernel<<<4096, 512>>>(rpb);
    conv_w_kernel<<<768, 32>>>(qkv_w);
    conv_a_kernel<<<4096, 256>>>(x);
    hmma_gemm_kernel<<<dim3(256, 6), 256, 81920>>>(qkv_b, nullptr, 0);
    conv_w_kernel<<<256, 32>>>(proj_w);
    attn_mma_kernel<<<2048, 128, 59392>>>();
    hmma_gemm_kernel<<<dim3(256, 2), 256, 81920>>>(proj_b, out, 1);
}

// round 14
// speedup vs baseline: 1.0510x; 1.0510x over previous
#include <cuda_runtime.h>
#include <cuda_bf16.h>
#include <math.h>
#include <stdint.h>

#define NWIN 64
#define NTOK 512
#define NHEAD 8
#define HDIM 32
#define CDIM 256
#define KCAT2 512           // [hi(256) | lo(256)]
#define MTOT 32768

#define LOG2E 1.4426950408889634f
#define QSCALE (0.17677669529663687f * 1.4426950408889634f)

__device__ __nv_bfloat16 g_qh[(size_t)512 * 512 * 32];
__device__ __nv_bfloat16 g_ql[(size_t)512 * 512 * 32];
__device__ __nv_bfloat16 g_kh[(size_t)512 * 512 * 32];
__device__ __nv_bfloat16 g_kl[(size_t)512 * 512 * 32];
__device__ __nv_bfloat16 g_vh[(size_t)512 * 512 * 32];   // [bx][tok][32] (NOT transposed)
__device__ __nv_bfloat16 g_vl[(size_t)512 * 512 * 32];
__device__ __nv_bfloat16 g_bfrag[(size_t)8 * 8 * 32 * 64 * 128];
__device__ int   g_tokoff[NWIN * NTOK];
__device__ __nv_bfloat16 g_acat[(size_t)MTOT * KCAT2];
__device__ __nv_bfloat16 g_bcat[(size_t)768 * KCAT2];

__device__ __forceinline__ uint32_t smem_u32(const void* p) {
    uint32_t a;
    asm("{ .reg .u64 t; cvta.to.shared.u64 t, %1; cvt.u32.u64 %0, t; }" : "=r"(a) : "l"(p));
    return a;
}
__device__ __forceinline__ void ldmx4(uint32_t* r, uint32_t addr) {
    asm volatile("ldmatrix.sync.aligned.m8n8.x4.shared.b16 {%0,%1,%2,%3}, [%4];"
                 : "=r"(r[0]), "=r"(r[1]), "=r"(r[2]), "=r"(r[3]) : "r"(addr));
}
__device__ __forceinline__ void ldmx4t(uint32_t* r, uint32_t addr) {
    asm volatile("ldmatrix.sync.aligned.m8n8.x4.trans.shared.b16 {%0,%1,%2,%3}, [%4];"
                 : "=r"(r[0]), "=r"(r[1]), "=r"(r[2]), "=r"(r[3]) : "r"(addr));
}
__device__ __forceinline__ void st128(uint32_t addr, uint4 v) {
    asm volatile("st.shared.v4.b32 [%0], {%1,%2,%3,%4};"
                 :: "r"(addr), "r"(v.x), "r"(v.y), "r"(v.z), "r"(v.w) : "memory");
}
__device__ __forceinline__ void mma16816(float* c, const uint32_t* a, const uint32_t* b) {
    asm volatile("mma.sync.aligned.m16n8k16.row.col.f32.bf16.bf16.f32 "
                 "{%0,%1,%2,%3}, {%4,%5,%6,%7}, {%8,%9}, {%0,%1,%2,%3};"
                 : "+f"(c[0]), "+f"(c[1]), "+f"(c[2]), "+f"(c[3])
                 : "r"(a[0]), "r"(a[1]), "r"(a[2]), "r"(a[3]), "r"(b[0]), "r"(b[1]));
}
// RN split (cold paths: conv, GEMM epilogue)
__device__ __forceinline__ void split2(float f0, float f1, uint32_t& hi, uint32_t& lo) {
    __nv_bfloat16 h0 = __float2bfloat16(f0), h1 = __float2bfloat16(f1);
    __nv_bfloat16 l0 = __float2bfloat16(f0 - __bfloat162float(h0));
    __nv_bfloat16 l1 = __float2bfloat16(f1 - __bfloat162float(h1));
    uint16_t uh0 = *(uint16_t*)&h0, uh1 = *(uint16_t*)&h1;
    uint16_t ul0 = *(uint16_t*)&l0, ul1 = *(uint16_t*)&l1;
    hi = (uint32_t)uh0 | ((uint32_t)uh1 << 16);
    lo = (uint32_t)ul0 | ((uint32_t)ul1 << 16);
}
// Truncation split (hot path: P in attention). hi = top 16 bits; lo exact diff.
__device__ __forceinline__ void split2_fast(float f0, float f1, uint32_t& hi, uint32_t& lo) {
    uint32_t u0 = __float_as_uint(f0), u1 = __float_as_uint(f1);
    float h0 = __uint_as_float(u0 & 0xFFFF0000u);
    float h1 = __uint_as_float(u1 & 0xFFFF0000u);
    asm("prmt.b32 %0, %1, %2, 0x7632;" : "=r"(hi) : "r"(u0), "r"(u1));
    asm("cvt.rn.bf16x2.f32 %0, %1, %2;" : "=r"(lo) : "f"(f1 - h1), "f"(f0 - h0));
}
#define CPA16(dst, src) \
    asm volatile("cp.async.cg.shared.global [%0], [%1], 16;" :: "r"(dst), "l"(src) : "memory")
#define CPC() asm volatile("cp.async.commit_group;" ::: "memory")
#define CPW0() asm volatile("cp.async.wait_group 0;" ::: "memory")

// ---------------------------------------------------------------------------
__global__ void prep_tok_kernel() {
    int gid = blockIdx.x * 256 + threadIdx.x;
    int w = gid >> 9, n = gid & 511;
    int wh = w >> 4, ww = (w >> 2) & 3, wd = w & 3;
    int ih = n >> 6, iw = (n >> 3) & 7, id = n & 7;
    int gh = (wh * 8 + ih + 4) & 31;
    int gw = (ww * 8 + iw + 4) & 31;
    int gd = (wd * 8 + id + 4) & 31;
    g_tokoff[gid] = ((gh * 32 + gw) * 32 + gd) * 256;
}

// ---------------------------------------------------------------------------
__global__ void __launch_bounds__(512) prep_bias_kernel(const float* __restrict__ rpb) {
    int cfg = blockIdx.x >> 9, i = blockIdx.x & 511;
    int h = threadIdx.x >> 6, jb = threadIdx.x & 63;
    int ch = (cfg >> 2) & 1, cw = (cfg >> 1) & 1, cd = cfg & 1;
    int i0 = i >> 6, i1 = (i >> 3) & 7, i2 = i & 7;
    int ri = (ch ? (i0 < 4 ? 1 : 2) : 0) * 9 + (cw ? (i1 < 4 ? 1 : 2) : 0) * 3
           + (cd ? (i2 < 4 ? 1 : 2) : 0);
    int ib = i >> 4, half = (i & 15) >> 3, row = i & 7;
    int j0 = jb >> 3, j1 = jb & 7;
    int rjb = (ch ? (j0 < 4 ? 1 : 2) : 0) * 9 + (cw ? (j1 < 4 ? 1 : 2) : 0) * 3;
    int idxb = (i0 - j0 + 7) * 225 + (i1 - j1 + 7) * 15;
    union { __nv_bfloat16 h8[8]; uint4 u; } O;
#pragma unroll
    for (int j2 = 0; j2 < 8; j2++) {
        int rj = rjb + (cd ? (j2 < 4 ? 1 : 2) : 0);
        int idx = idxb + (i2 - j2 + 7);
        float m = (ri == rj) ? 0.f : -100.f;
        O.h8[j2] = __float2bfloat16((rpb[idx * 8 + h] + m) * LOG2E);
    }
    size_t base = (((((size_t)cfg * 8 + h) * 32 + ib) * 64 + jb) * 128) + half * 64 + row * 8;
    *(uint4*)(g_bfrag + base) = O.u;
}

// ---------------------------------------------------------------------------
__global__ void conv_a_kernel(const float* __restrict__ src) {
    int row = blockIdx.x * 8 + (threadIdx.x >> 5);
    int c8 = (threadIdx.x & 31) * 8;
    const float* sp = src + g_tokoff[row];
    float4 v0 = *(const float4*)(sp + c8);
    float4 v1 = *(const float4*)(sp + c8 + 4);
    float f[8] = {v0.x, v0.y, v0.z, v0.w, v1.x, v1.y, v1.z, v1.w};
    union { __nv_bfloat16 h[8]; uint4 u; } H, L;
#pragma unroll
    for (int i = 0; i < 8; i++) {
        H.h[i] = __float2bfloat16(f[i]);
        L.h[i] = __float2bfloat16(f[i] - __bfloat162float(H.h[i]));
    }
    __nv_bfloat16* dst = g_acat + (size_t)row * KCAT2;
    *(uint4*)(dst + c8)       = H.u;
    *(uint4*)(dst + 256 + c8) = L.u;
}

__global__ void conv_w_kernel(const float* __restrict__ W) {
    int row = blockIdx.x;
    int c8 = threadIdx.x * 8;
    const float* sp = W + (size_t)row * 256 + c8;
    float4 v0 = *(const float4*)(sp);
    float4 v1 = *(const float4*)(sp + 4);
    float f[8] = {v0.x, v0.y, v0.z, v0.w, v1.x, v1.y, v1.z, v1.w};
    union { __nv_bfloat16 h[8]; uint4 u; } H, L;
#pragma unroll
    for (int i = 0; i < 8; i++) {
        H.h[i] = __float2bfloat16(f[i]);
        L.h[i] = __float2bfloat16(f[i] - __bfloat162float(H.h[i]));
    }
    __nv_bfloat16* dst = g_bcat + (size_t)row * KCAT2;
    *(uint4*)(dst + c8)       = H.u;
    *(uint4*)(dst + 256 + c8) = L.u;
}

// ---------------------------------------------------------------------------
// HMMA GEMM (R12 superchunk mainloop; v-epilogue now identical to q/k).
// ---------------------------------------------------------------------------
__global__ void __launch_bounds__(256, 2) hmma_gemm_kernel(const float* __restrict__ bias,
                                                           float* __restrict__ out, int mode) {
    extern __shared__ __align__(16) char smem[];
    uint32_t sbase = smem_u32(smem);
    int tid = threadIdx.x;
    int lane = tid & 31, wid = tid >> 5;
    int wm = wid & 3, wn = wid >> 2;
    int m0 = blockIdx.x * 128, n0 = blockIdx.y * 128;

    int lr = tid >> 1, lh = tid & 1;
    const char* Arow = (const char*)g_acat + (size_t)(m0 + lr) * 1024;
    const char* Brow = (const char*)g_bcat + (size_t)(n0 + lr) * 1024;
    uint32_t stoff = (uint32_t)(lr * 80 + lh * 32);

    const uint32_t AH = 0, AL = 10240, BH = 20480, BL = 30720;

    auto issue = [&](int n) {
        uint32_t st = sbase + (uint32_t)(n & 1) * 40960u;
        int so = n * 64 + lh * 32;
#pragma unroll
        for (int i = 0; i < 2; i++) {
            CPA16(st + AH + stoff + i * 16, Arow + so + i * 16);
            CPA16(st + AL + stoff + i * 16, Arow + 512 + so + i * 16);
            CPA16(st + BH + stoff + i * 16, Brow + so + i * 16);
            CPA16(st + BL + stoff + i * 16, Brow + 512 + so + i * 16);
        }
        CPC();
    };

    uint32_t aoff = (uint32_t)((((lane & 7) + ((lane >> 3) & 1) * 8) * 80) + (lane >> 4) * 16);
    uint32_t boff = (uint32_t)((((lane & 7) + (lane >> 4) * 8) * 80) + ((lane >> 3) & 1) * 16);

    float acc[2][8][4];
#pragma unroll
    for (int a = 0; a < 2; a++)
#pragma unroll
        for (int b = 0; b < 8; b++)
#pragma unroll
            for (int c = 0; c < 4; c++) acc[a][b][c] = 0.f;

    issue(0);
    CPW0();
    __syncthreads();

#pragma unroll 1
    for (int c = 0; c < 8; c++) {
        if (c < 7) issue(c + 1);

        uint32_t st = sbase + (uint32_t)(c & 1) * 40960u;
        uint32_t AHw = st + AH + (uint32_t)(wm * 32) * 80u + aoff;
        uint32_t ALw = st + AL + (uint32_t)(wm * 32) * 80u + aoff;
        uint32_t BHw = st + BH + (uint32_t)(wn * 64) * 80u + boff;
        uint32_t BLw = st + BL + (uint32_t)(wn * 64) * 80u + boff;
#pragma unroll
        for (int ks = 0; ks < 2; ks++) {
            uint32_t ah[2][4], al[2][4];
#pragma unroll
            for (int mt = 0; mt < 2; mt++) {
                ldmx4(ah[mt], AHw + (uint32_t)(mt * 16) * 80u + ks * 32u);
                ldmx4(al[mt], ALw + (uint32_t)(mt * 16) * 80u + ks * 32u);
            }
            uint32_t bh[8][2];
#pragma unroll
            for (int p = 0; p < 4; p++) {
                uint32_t t4[4];
                ldmx4(t4, BHw + (uint32_t)(p * 16) * 80u + ks * 32u);
                bh[2 * p][0] = t4[0]; bh[2 * p][1] = t4[1];
                bh[2 * p + 1][0] = t4[2]; bh[2 * p + 1][1] = t4[3];
            }
#pragma unroll
            for (int mt = 0; mt < 2; mt++)
#pragma unroll
                for (int nt = 0; nt < 8; nt++) {
                    mma16816(acc[mt][nt], ah[mt], bh[nt]);
                    mma16816(acc[mt][nt], al[mt], bh[nt]);
                }
            uint32_t bl[8][2];
#pragma unroll
            for (int p = 0; p < 4; p++) {
                uint32_t t4[4];
                ldmx4(t4, BLw + (uint32_t)(p * 16) * 80u + ks * 32u);
                bl[2 * p][0] = t4[0]; bl[2 * p][1] = t4[1];
                bl[2 * p + 1][0] = t4[2]; bl[2 * p + 1][1] = t4[3];
            }
#pragma unroll
            for (int mt = 0; mt < 2; mt++)
#pragma unroll
                for (int nt = 0; nt < 8; nt++)
                    mma16816(acc[mt][nt], ah[mt], bl[nt]);
        }
        if (c < 7) {
            CPW0();
            __syncthreads();
        }
    }

    int quad = lane >> 2, tg = lane & 3;
#pragma unroll
    for (int mt = 0; mt < 2; mt++) {
        int rbase = m0 + wm * 32 + mt * 16 + quad;
#pragma unroll
        for (int nt = 0; nt < 8; nt++) {
            int col = n0 + wn * 64 + nt * 8 + tg * 2;
            float2 bb = *(const float2*)(bias + col);
            if (mode == 0) {
                int sec = n0 >> 8;
                float sc = (sec == 0) ? QSCALE : 1.0f;
                int head = (col & 255) >> 5, dd = col & 31;
                __nv_bfloat16* bh_ = (sec == 0) ? g_qh : ((sec == 1) ? g_kh : g_vh);
                __nv_bfloat16* bl_ = (sec == 0) ? g_ql : ((sec == 1) ? g_kl : g_vl);
#pragma unroll
                for (int hf = 0; hf < 2; hf++) {
                    int rr = rbase + hf * 8;
                    int w = rr >> 9, nn = rr & 511;
                    size_t bxi = (size_t)(w * 8 + head);
                    float f0 = (acc[mt][nt][hf * 2 + 0] + bb.x) * sc;
                    float f1 = (acc[mt][nt][hf * 2 + 1] + bb.y) * sc;
                    uint32_t hi, lo;
                    split2(f0, f1, hi, lo);
                    *(uint32_t*)(bh_ + (bxi * 512 + nn) * 32 + dd) = hi;
                    *(uint32_t*)(bl_ + (bxi * 512 + nn) * 32 + dd) = lo;
                }
            } else {
#pragma unroll
                for (int hf = 0; hf < 2; hf++) {
                    int rr = rbase + hf * 8;
                    int off = g_tokoff[rr] + col;
                    float2 o;
                    o.x = acc[mt][nt][hf * 2 + 0] + bb.x;
                    o.y = acc[mt][nt][hf * 2 + 1] + bb.y;
                    *(float2*)(out + off) = o;
                }
            }
        }
    }
}

// ---------------------------------------------------------------------------
// HMMA attention (R12 shape: 8 warps x 16 rows, double buffer).
// V now loaded from [tok][32] layout via ldmatrix.trans; P split truncated.
// smem: Qh 10240 | Ql 10240 | 2 x (KH KL VH VL each 64x80=5120 -> 20480).
// Total 61440.
// ---------------------------------------------------------------------------
__global__ void __launch_bounds__(256, 2) attn_mma_kernel() {
    extern __shared__ __align__(16) char sm[];
    uint32_t sb = smem_u32(sm);
    const int tid = threadIdx.x, lane = tid & 31, wid = tid >> 5;
    int bx = blockIdx.x >> 2, mtile = blockIdx.x & 3;
    int w = bx >> 3, h = bx & 7;
    int cfg = (((w >> 4) == 3) ? 4 : 0) | ((((w >> 2) & 3) == 3) ? 2 : 0) | (((w & 3) == 3) ? 1 : 0);

    const uint32_t SQH = 0, SQL = 10240, SBUF = 20480, BSTR = 20480;
    const uint32_t KH = 0, KL = 5120, VH = 10240, VL = 15360;

    int row_k = tid >> 2, seg_k = tid & 3;
    const char* kga = (const char*)g_kh + (size_t)bx * 32768 + row_k * 64 + seg_k * 16;
    const char* kgb = (const char*)g_kl + (size_t)bx * 32768 + row_k * 64 + seg_k * 16;
    const char* vga = (const char*)g_vh + (size_t)bx * 32768 + row_k * 64 + seg_k * 16;
    const char* vgb = (const char*)g_vl + (size_t)bx * 32768 + row_k * 64 + seg_k * 16;
    uint32_t kdst = row_k * 80 + seg_k * 16;

    auto issueKV = [&](int n) {
        uint32_t B2 = sb + SBUF + (uint32_t)(n & 1) * BSTR;
        CPA16(B2 + KH + kdst, kga + (size_t)n * 4096);
        CPA16(B2 + KL + kdst, kgb + (size_t)n * 4096);
        CPA16(B2 + VH + kdst, vga + (size_t)n * 4096);
        CPA16(B2 + VL + kdst, vgb + (size_t)n * 4096);
        CPC();
    };

    issueKV(0);

#pragma unroll
    for (int u = 0; u < 2; u++) {
        int lin = tid + u * 256;
        int row = lin >> 2, seg = lin & 3;
        size_t src = ((size_t)bx * 512 + mtile * 128 + row) * 32 + seg * 8;
        st128(sb + SQH + row * 80 + seg * 16, *(const uint4*)(g_qh + src));
        st128(sb + SQL + row * 80 + seg * 16, *(const uint4*)(g_ql + src));
    }
    CPW0();
    __syncthreads();

    uint32_t aoff = (uint32_t)(((lane & 7) + ((lane >> 3) & 1) * 8) * 80 + (lane >> 4) * 16);
    uint32_t boff = (uint32_t)(((lane & 7) + (lane >> 4) * 8) * 80 + ((lane >> 3) & 1) * 16);
    uint32_t qh[2][4], ql[2][4];
#pragma unroll
    for (int ks = 0; ks < 2; ks++) {
        ldmx4(qh[ks], sb + SQH + (uint32_t)(wid * 16) * 80 + aoff + ks * 32);
        ldmx4(ql[ks], sb + SQL + (uint32_t)(wid * 16) * 80 + aoff + ks * 32);
    }

    float oacc[4][4];
#pragma unroll
    for (int a = 0; a < 4; a++)
#pragma unroll
        for (int b = 0; b < 4; b++) oacc[a][b] = 0.f;
    float rs0 = 0.f, rs1 = 0.f;
    int quad = lane >> 2, tg = lane & 3;
    int ib = mtile * 8 + wid;
    const __nv_bfloat16* bf = g_bfrag + ((((size_t)cfg * 8 + h) * 32 + ib) * 64) * 128;

#pragma unroll 1
    for (int jt = 0; jt < 8; jt++) {
        if (jt < 7) issueKV(jt + 1);
        uint32_t B = sb + SBUF + (uint32_t)(jt & 1) * BSTR;

        float sacc[8][4];
#pragma unroll
        for (int a = 0; a < 8; a++)
#pragma unroll
            for (int b = 0; b < 4; b++) sacc[a][b] = 0.f;
#pragma unroll
        for (int ks = 0; ks < 2; ks++)
#pragma unroll
            for (int p = 0; p < 4; p++) {
                uint32_t bh[4], bl[4];
                ldmx4(bh, B + KH + (uint32_t)(p * 16) * 80 + boff + ks * 32);
                ldmx4(bl, B + KL + (uint32_t)(p * 16) * 80 + boff + ks * 32);
#pragma unroll
                for (int n2 = 0; n2 < 2; n2++) {
                    mma16816(sacc[2 * p + n2], qh[ks], &bh[n2 * 2]);
                    mma16816(sacc[2 * p + n2], qh[ks], &bl[n2 * 2]);
                    mma16816(sacc[2 * p + n2], ql[ks], &bh[n2 * 2]);
                }
            }

        uint32_t aPhi[4][4], aPlo[4][4];
#pragma unroll
        for (int nt = 0; nt < 8; nt++) {
            const uint32_t* bp = (const uint32_t*)(bf + (size_t)(jt * 8 + nt) * 128);
            __nv_bfloat162 bb01 = *(const __nv_bfloat162*)&bp[quad * 4 + tg];
            __nv_bfloat162 bb23 = *(const __nv_bfloat162*)&bp[32 + quad * 4 + tg];
            float2 b01 = __bfloat1622float2(bb01);
            float2 b23 = __bfloat1622float2(bb23);
            float p0 = exp2f(sacc[nt][0] + b01.x);
            float p1 = exp2f(sacc[nt][1] + b01.y);
            float p2 = exp2f(sacc[nt][2] + b23.x);
            float p3 = exp2f(sacc[nt][3] + b23.y);
            rs0 += p0 + p1;
            rs1 += p2 + p3;
            int kt = nt >> 1, o = (nt & 1) * 2;
            split2_fast(p0, p1, aPhi[kt][o], aPlo[kt][o]);
            split2_fast(p2, p3, aPhi[kt][o + 1], aPlo[kt][o + 1]);
        }

        // PV: V via ldmatrix.trans from [tok][32] tiles (rows = j, 64B)
#pragma unroll
        for (int kt = 0; kt < 4; kt++) {
            uint32_t vh[4][2], vl[4][2];
#pragma unroll
            for (int dp = 0; dp < 2; dp++) {
                uint32_t t4[4];
                ldmx4t(t4, B + VH + (uint32_t)(kt * 16) * 80 + aoff + dp * 32);
                vh[dp * 2][0] = t4[0]; vh[dp * 2][1] = t4[1];
                vh[dp * 2 + 1][0] = t4[2]; vh[dp * 2 + 1][1] = t4[3];
                ldmx4t(t4, B + VL + (uint32_t)(kt * 16) * 80 + aoff + dp * 32);
                vl[dp * 2][0] = t4[0]; vl[dp * 2][1] = t4[1];
                vl[dp * 2 + 1][0] = t4[2]; vl[dp * 2 + 1][1] = t4[3];
            }
#pragma unroll
            for (int nb = 0; nb < 4; nb++) {
                mma16816(oacc[nb], aPhi[kt], vh[nb]);
                mma16816(oacc[nb], aPhi[kt], vl[nb]);
                mma16816(oacc[nb], aPlo[kt], vh[nb]);
            }
        }

        if (jt < 7) {
            CPW0();
            __syncthreads();
        }
    }

    rs0 += __shfl_xor_sync(0xFFFFFFFF, rs0, 1);
    rs0 += __shfl_xor_sync(0xFFFFFFFF, rs0, 2);
    rs1 += __shfl_xor_sync(0xFFFFFFFF, rs1, 1);
    rs1 += __shfl_xor_sync(0xFFFFFFFF, rs1, 2);
    float inv0 = 1.f / rs0, inv1 = 1.f / rs1;
    int qtok = mtile * 128 + wid * 16 + quad;
    int t0 = w * 512 + qtok, t1 = t0 + 8;
#pragma unroll
    for (int nt = 0; nt < 4; nt++) {
        int c = h * 32 + nt * 8 + tg * 2;
        uint32_t hi, lo;
        split2(oacc[nt][0] * inv0, oacc[nt][1] * inv0, hi, lo);
        __nv_bfloat16* d0 = g_acat + (size_t)t0 * KCAT2 + c;
        *(uint32_t*)d0         = hi;
        *(uint32_t*)(d0 + 256) = lo;
        split2(oacc[nt][2] * inv1, oacc[nt][3] * inv1, hi, lo);
        __nv_bfloat16* d1 = g_acat + (size_t)t1 * KCAT2 + c;
        *(uint32_t*)d1         = hi;
        *(uint32_t*)(d1 + 256) = lo;
    }
}

extern "C" void kernel_launch(void* const* d_in, const int* in_sizes, int n_in,
                              void* d_out, int out_size) {
    const float* x      = (const float*)d_in[0];
    const float* qkv_w  = (const float*)d_in[1];
    const float* qkv_b  = (const float*)d_in[2];
    const float* proj_w = (const float*)d_in[3];
    const float* proj_b = (const float*)d_in[4];
    const float* rpb    = (const float*)d_in[5];
    float* out = (float*)d_out;

    cudaFuncSetAttribute(hmma_gemm_kernel, cudaFuncAttributeMaxDynamicSharedMemorySize, 81920);
    cudaFuncSetAttribute(attn_mma_kernel, cudaFuncAttributeMaxDynamicSharedMemorySize, 61440);

    prep_tok_kernel<<<128, 256>>>();
    prep_bias_kernel<<<4096, 512>>>(rpb);
    conv_w_kernel<<<768, 32>>>(qkv_w);
    conv_a_kernel<<<4096, 256>>>(x);
    hmma_gemm_kernel<<<dim3(256, 6), 256, 81920>>>(qkv_b, nullptr, 0);
    conv_w_kernel<<<256, 32>>>(proj_w);
    attn_mma_kernel<<<2048, 256, 61440>>>();
    hmma_gemm_kernel<<<dim3(256, 2), 256, 81920>>>(proj_b, out, 1);
}

// round 15
// speedup vs baseline: 1.1403x; 1.0850x over previous
#include <cuda_runtime.h>
#include <cuda_bf16.h>
#include <cuda_fp16.h>
#include <math.h>
#include <stdint.h>

#define NWIN 64
#define NTOK 512
#define NHEAD 8
#define HDIM 32
#define CDIM 256
#define KCAT2 512           // [hi(256) | lo(256)]
#define MTOT 32768

#define LOG2E 1.4426950408889634f
#define QSCALE (0.17677669529663687f * 1.4426950408889634f)

__device__ __nv_bfloat16 g_qh[(size_t)512 * 512 * 32];
__device__ __nv_bfloat16 g_ql[(size_t)512 * 512 * 32];
__device__ __nv_bfloat16 g_kh[(size_t)512 * 512 * 32];
__device__ __nv_bfloat16 g_kl[(size_t)512 * 512 * 32];
__device__ __half g_vh[(size_t)512 * 512 * 32];          // fp16 V hi, [bx][tok][32]
__device__ __half g_vl[(size_t)512 * 512 * 32];          // fp16 V lo
__device__ __nv_bfloat16 g_bfrag[(size_t)8 * 8 * 32 * 64 * 128];
__device__ int   g_tokoff[NWIN * NTOK];
__device__ __nv_bfloat16 g_acat[(size_t)MTOT * KCAT2];
__device__ __nv_bfloat16 g_bcat[(size_t)768 * KCAT2];

__device__ __forceinline__ uint32_t smem_u32(const void* p) {
    uint32_t a;
    asm("{ .reg .u64 t; cvta.to.shared.u64 t, %1; cvt.u32.u64 %0, t; }" : "=r"(a) : "l"(p));
    return a;
}
__device__ __forceinline__ void ldmx4(uint32_t* r, uint32_t addr) {
    asm volatile("ldmatrix.sync.aligned.m8n8.x4.shared.b16 {%0,%1,%2,%3}, [%4];"
                 : "=r"(r[0]), "=r"(r[1]), "=r"(r[2]), "=r"(r[3]) : "r"(addr));
}
__device__ __forceinline__ void ldmx4t(uint32_t* r, uint32_t addr) {
    asm volatile("ldmatrix.sync.aligned.m8n8.x4.trans.shared.b16 {%0,%1,%2,%3}, [%4];"
                 : "=r"(r[0]), "=r"(r[1]), "=r"(r[2]), "=r"(r[3]) : "r"(addr));
}
__device__ __forceinline__ void st128(uint32_t addr, uint4 v) {
    asm volatile("st.shared.v4.b32 [%0], {%1,%2,%3,%4};"
                 :: "r"(addr), "r"(v.x), "r"(v.y), "r"(v.z), "r"(v.w) : "memory");
}
__device__ __forceinline__ void mma16816(float* c, const uint32_t* a, const uint32_t* b) {
    asm volatile("mma.sync.aligned.m16n8k16.row.col.f32.bf16.bf16.f32 "
                 "{%0,%1,%2,%3}, {%4,%5,%6,%7}, {%8,%9}, {%0,%1,%2,%3};"
                 : "+f"(c[0]), "+f"(c[1]), "+f"(c[2]), "+f"(c[3])
                 : "r"(a[0]), "r"(a[1]), "r"(a[2]), "r"(a[3]), "r"(b[0]), "r"(b[1]));
}
__device__ __forceinline__ void mma16816h(float* c, const uint32_t* a, const uint32_t* b) {
    asm volatile("mma.sync.aligned.m16n8k16.row.col.f32.f16.f16.f32 "
                 "{%0,%1,%2,%3}, {%4,%5,%6,%7}, {%8,%9}, {%0,%1,%2,%3};"
                 : "+f"(c[0]), "+f"(c[1]), "+f"(c[2]), "+f"(c[3])
                 : "r"(a[0]), "r"(a[1]), "r"(a[2]), "r"(a[3]), "r"(b[0]), "r"(b[1]));
}
// RN bf16 split (conv, q/k epilogue, attention out epilogue)
__device__ __forceinline__ void split2(float f0, float f1, uint32_t& hi, uint32_t& lo) {
    __nv_bfloat16 h0 = __float2bfloat16(f0), h1 = __float2bfloat16(f1);
    __nv_bfloat16 l0 = __float2bfloat16(f0 - __bfloat162float(h0));
    __nv_bfloat16 l1 = __float2bfloat16(f1 - __bfloat162float(h1));
    uint16_t uh0 = *(uint16_t*)&h0, uh1 = *(uint16_t*)&h1;
    uint16_t ul0 = *(uint16_t*)&l0, ul1 = *(uint16_t*)&l1;
    hi = (uint32_t)uh0 | ((uint32_t)uh1 << 16);
    lo = (uint32_t)ul0 | ((uint32_t)ul1 << 16);
}
// RN fp16 split (v epilogue)
__device__ __forceinline__ void split2h(float f0, float f1, uint32_t& hi, uint32_t& lo) {
    __half h0 = __float2half_rn(f0), h1 = __float2half_rn(f1);
    __half l0 = __float2half_rn(f0 - __half2float(h0));
    __half l1 = __float2half_rn(f1 - __half2float(h1));
    uint16_t uh0 = *(uint16_t*)&h0, uh1 = *(uint16_t*)&h1;
    uint16_t ul0 = *(uint16_t*)&l0, ul1 = *(uint16_t*)&l1;
    hi = (uint32_t)uh0 | ((uint32_t)uh1 << 16);
    lo = (uint32_t)ul0 | ((uint32_t)ul1 << 16);
}
// pack two floats into fp16x2 (f0 low, f1 high)
__device__ __forceinline__ uint32_t pack_f16x2(float f0, float f1) {
    uint32_t r;
    asm("cvt.rn.f16x2.f32 %0, %1, %2;" : "=r"(r) : "f"(f1), "f"(f0));
    return r;
}
#define CPA16(dst, src) \
    asm volatile("cp.async.cg.shared.global [%0], [%1], 16;" :: "r"(dst), "l"(src) : "memory")
#define CPC() asm volatile("cp.async.commit_group;" ::: "memory")
#define CPW0() asm volatile("cp.async.wait_group 0;" ::: "memory")

// ---------------------------------------------------------------------------
__global__ void prep_tok_kernel() {
    int gid = blockIdx.x * 256 + threadIdx.x;
    int w = gid >> 9, n = gid & 511;
    int wh = w >> 4, ww = (w >> 2) & 3, wd = w & 3;
    int ih = n >> 6, iw = (n >> 3) & 7, id = n & 7;
    int gh = (wh * 8 + ih + 4) & 31;
    int gw = (ww * 8 + iw + 4) & 31;
    int gd = (wd * 8 + id + 4) & 31;
    g_tokoff[gid] = ((gh * 32 + gw) * 32 + gd) * 256;
}

// ---------------------------------------------------------------------------
__global__ void __launch_bounds__(512) prep_bias_kernel(const float* __restrict__ rpb) {
    int cfg = blockIdx.x >> 9, i = blockIdx.x & 511;
    int h = threadIdx.x >> 6, jb = threadIdx.x & 63;
    int ch = (cfg >> 2) & 1, cw = (cfg >> 1) & 1, cd = cfg & 1;
    int i0 = i >> 6, i1 = (i >> 3) & 7, i2 = i & 7;
    int ri = (ch ? (i0 < 4 ? 1 : 2) : 0) * 9 + (cw ? (i1 < 4 ? 1 : 2) : 0) * 3
           + (cd ? (i2 < 4 ? 1 : 2) : 0);
    int ib = i >> 4, half = (i & 15) >> 3, row = i & 7;
    int j0 = jb >> 3, j1 = jb & 7;
    int rjb = (ch ? (j0 < 4 ? 1 : 2) : 0) * 9 + (cw ? (j1 < 4 ? 1 : 2) : 0) * 3;
    int idxb = (i0 - j0 + 7) * 225 + (i1 - j1 + 7) * 15;
    union { __nv_bfloat16 h8[8]; uint4 u; } O;
#pragma unroll
    for (int j2 = 0; j2 < 8; j2++) {
        int rj = rjb + (cd ? (j2 < 4 ? 1 : 2) : 0);
        int idx = idxb + (i2 - j2 + 7);
        float m = (ri == rj) ? 0.f : -100.f;
        O.h8[j2] = __float2bfloat16((rpb[idx * 8 + h] + m) * LOG2E);
    }
    size_t base = (((((size_t)cfg * 8 + h) * 32 + ib) * 64 + jb) * 128) + half * 64 + row * 8;
    *(uint4*)(g_bfrag + base) = O.u;
}

// ---------------------------------------------------------------------------
__global__ void conv_a_kernel(const float* __restrict__ src) {
    int row = blockIdx.x * 8 + (threadIdx.x >> 5);
    int c8 = (threadIdx.x & 31) * 8;
    const float* sp = src + g_tokoff[row];
    float4 v0 = *(const float4*)(sp + c8);
    float4 v1 = *(const float4*)(sp + c8 + 4);
    float f[8] = {v0.x, v0.y, v0.z, v0.w, v1.x, v1.y, v1.z, v1.w};
    union { __nv_bfloat16 h[8]; uint4 u; } H, L;
#pragma unroll
    for (int i = 0; i < 8; i++) {
        H.h[i] = __float2bfloat16(f[i]);
        L.h[i] = __float2bfloat16(f[i] - __bfloat162float(H.h[i]));
    }
    __nv_bfloat16* dst = g_acat + (size_t)row * KCAT2;
    *(uint4*)(dst + c8)       = H.u;
    *(uint4*)(dst + 256 + c8) = L.u;
}

__global__ void conv_w_kernel(const float* __restrict__ W) {
    int row = blockIdx.x;
    int c8 = threadIdx.x * 8;
    const float* sp = W + (size_t)row * 256 + c8;
    float4 v0 = *(const float4*)(sp);
    float4 v1 = *(const float4*)(sp + 4);
    float f[8] = {v0.x, v0.y, v0.z, v0.w, v1.x, v1.y, v1.z, v1.w};
    union { __nv_bfloat16 h[8]; uint4 u; } H, L;
#pragma unroll
    for (int i = 0; i < 8; i++) {
        H.h[i] = __float2bfloat16(f[i]);
        L.h[i] = __float2bfloat16(f[i] - __bfloat162float(H.h[i]));
    }
    __nv_bfloat16* dst = g_bcat + (size_t)row * KCAT2;
    *(uint4*)(dst + c8)       = H.u;
    *(uint4*)(dst + 256 + c8) = L.u;
}

// ---------------------------------------------------------------------------
// HMMA GEMM (R12 superchunk mainloop; v-epilogue emits fp16 hi/lo).
// ---------------------------------------------------------------------------
__global__ void __launch_bounds__(256, 2) hmma_gemm_kernel(const float* __restrict__ bias,
                                                           float* __restrict__ out, int mode) {
    extern __shared__ __align__(16) char smem[];
    uint32_t sbase = smem_u32(smem);
    int tid = threadIdx.x;
    int lane = tid & 31, wid = tid >> 5;
    int wm = wid & 3, wn = wid >> 2;
    int m0 = blockIdx.x * 128, n0 = blockIdx.y * 128;

    int lr = tid >> 1, lh = tid & 1;
    const char* Arow = (const char*)g_acat + (size_t)(m0 + lr) * 1024;
    const char* Brow = (const char*)g_bcat + (size_t)(n0 + lr) * 1024;
    uint32_t stoff = (uint32_t)(lr * 80 + lh * 32);

    const uint32_t AH = 0, AL = 10240, BH = 20480, BL = 30720;

    auto issue = [&](int n) {
        uint32_t st = sbase + (uint32_t)(n & 1) * 40960u;
        int so = n * 64 + lh * 32;
#pragma unroll
        for (int i = 0; i < 2; i++) {
            CPA16(st + AH + stoff + i * 16, Arow + so + i * 16);
            CPA16(st + AL + stoff + i * 16, Arow + 512 + so + i * 16);
            CPA16(st + BH + stoff + i * 16, Brow + so + i * 16);
            CPA16(st + BL + stoff + i * 16, Brow + 512 + so + i * 16);
        }
        CPC();
    };

    uint32_t aoff = (uint32_t)((((lane & 7) + ((lane >> 3) & 1) * 8) * 80) + (lane >> 4) * 16);
    uint32_t boff = (uint32_t)((((lane & 7) + (lane >> 4) * 8) * 80) + ((lane >> 3) & 1) * 16);

    float acc[2][8][4];
#pragma unroll
    for (int a = 0; a < 2; a++)
#pragma unroll
        for (int b = 0; b < 8; b++)
#pragma unroll
            for (int c = 0; c < 4; c++) acc[a][b][c] = 0.f;

    issue(0);
    CPW0();
    __syncthreads();

#pragma unroll 1
    for (int c = 0; c < 8; c++) {
        if (c < 7) issue(c + 1);

        uint32_t st = sbase + (uint32_t)(c & 1) * 40960u;
        uint32_t AHw = st + AH + (uint32_t)(wm * 32) * 80u + aoff;
        uint32_t ALw = st + AL + (uint32_t)(wm * 32) * 80u + aoff;
        uint32_t BHw = st + BH + (uint32_t)(wn * 64) * 80u + boff;
        uint32_t BLw = st + BL + (uint32_t)(wn * 64) * 80u + boff;
#pragma unroll
        for (int ks = 0; ks < 2; ks++) {
            uint32_t ah[2][4], al[2][4];
#pragma unroll
            for (int mt = 0; mt < 2; mt++) {
                ldmx4(ah[mt], AHw + (uint32_t)(mt * 16) * 80u + ks * 32u);
                ldmx4(al[mt], ALw + (uint32_t)(mt * 16) * 80u + ks * 32u);
            }
            uint32_t bh[8][2];
#pragma unroll
            for (int p = 0; p < 4; p++) {
                uint32_t t4[4];
                ldmx4(t4, BHw + (uint32_t)(p * 16) * 80u + ks * 32u);
                bh[2 * p][0] = t4[0]; bh[2 * p][1] = t4[1];
                bh[2 * p + 1][0] = t4[2]; bh[2 * p + 1][1] = t4[3];
            }
#pragma unroll
            for (int mt = 0; mt < 2; mt++)
#pragma unroll
                for (int nt = 0; nt < 8; nt++) {
                    mma16816(acc[mt][nt], ah[mt], bh[nt]);
                    mma16816(acc[mt][nt], al[mt], bh[nt]);
                }
            uint32_t bl[8][2];
#pragma unroll
            for (int p = 0; p < 4; p++) {
                uint32_t t4[4];
                ldmx4(t4, BLw + (uint32_t)(p * 16) * 80u + ks * 32u);
                bl[2 * p][0] = t4[0]; bl[2 * p][1] = t4[1];
                bl[2 * p + 1][0] = t4[2]; bl[2 * p + 1][1] = t4[3];
            }
#pragma unroll
            for (int mt = 0; mt < 2; mt++)
#pragma unroll
                for (int nt = 0; nt < 8; nt++)
                    mma16816(acc[mt][nt], ah[mt], bl[nt]);
        }
        if (c < 7) {
            CPW0();
            __syncthreads();
        }
    }

    int quad = lane >> 2, tg = lane & 3;
#pragma unroll
    for (int mt = 0; mt < 2; mt++) {
        int rbase = m0 + wm * 32 + mt * 16 + quad;
#pragma unroll
        for (int nt = 0; nt < 8; nt++) {
            int col = n0 + wn * 64 + nt * 8 + tg * 2;
            float2 bb = *(const float2*)(bias + col);
            if (mode == 0) {
                int sec = n0 >> 8;
                float sc = (sec == 0) ? QSCALE : 1.0f;
                int head = (col & 255) >> 5, dd = col & 31;
#pragma unroll
                for (int hf = 0; hf < 2; hf++) {
                    int rr = rbase + hf * 8;
                    int w = rr >> 9, nn = rr & 511;
                    size_t bxi = (size_t)(w * 8 + head);
                    size_t eoff = (bxi * 512 + nn) * 32 + dd;
                    float f0 = (acc[mt][nt][hf * 2 + 0] + bb.x) * sc;
                    float f1 = (acc[mt][nt][hf * 2 + 1] + bb.y) * sc;
                    uint32_t hi, lo;
                    if (sec <= 1) {
                        split2(f0, f1, hi, lo);
                        *(uint32_t*)((sec == 0 ? g_qh : g_kh) + eoff) = hi;
                        *(uint32_t*)((sec == 0 ? g_ql : g_kl) + eoff) = lo;
                    } else {
                        split2h(f0, f1, hi, lo);
                        *(uint32_t*)(g_vh + eoff) = hi;
                        *(uint32_t*)(g_vl + eoff) = lo;
                    }
                }
            } else {
#pragma unroll
                for (int hf = 0; hf < 2; hf++) {
                    int rr = rbase + hf * 8;
                    int off = g_tokoff[rr] + col;
                    float2 o;
                    o.x = acc[mt][nt][hf * 2 + 0] + bb.x;
                    o.y = acc[mt][nt][hf * 2 + 1] + bb.y;
                    *(float2*)(out + off) = o;
                }
            }
        }
    }
}

// ---------------------------------------------------------------------------
// HMMA attention: QK bf16 3-term (unchanged); PV fp16 single-P 2-term
// (P*Vh + P*Vl, error ~2^-12). V via ldmatrix.trans from [tok][32] fp16.
// smem: Qh 10240 | Ql 10240 | 2 x (KH KL VH VL 5120 each = 20480). 61440 B.
// ---------------------------------------------------------------------------
__global__ void __launch_bounds__(256, 2) attn_mma_kernel() {
    extern __shared__ __align__(16) char sm[];
    uint32_t sb = smem_u32(sm);
    const int tid = threadIdx.x, lane = tid & 31, wid = tid >> 5;
    int bx = blockIdx.x >> 2, mtile = blockIdx.x & 3;
    int w = bx >> 3, h = bx & 7;
    int cfg = (((w >> 4) == 3) ? 4 : 0) | ((((w >> 2) & 3) == 3) ? 2 : 0) | (((w & 3) == 3) ? 1 : 0);

    const uint32_t SQH = 0, SQL = 10240, SBUF = 20480, BSTR = 20480;
    const uint32_t KH = 0, KL = 5120, VH = 10240, VL = 15360;

    int row_k = tid >> 2, seg_k = tid & 3;
    const char* kga = (const char*)g_kh + (size_t)bx * 32768 + row_k * 64 + seg_k * 16;
    const char* kgb = (const char*)g_kl + (size_t)bx * 32768 + row_k * 64 + seg_k * 16;
    const char* vga = (const char*)g_vh + (size_t)bx * 32768 + row_k * 64 + seg_k * 16;
    const char* vgb = (const char*)g_vl + (size_t)bx * 32768 + row_k * 64 + seg_k * 16;
    uint32_t kdst = row_k * 80 + seg_k * 16;

    auto issueKV = [&](int n) {
        uint32_t B2 = sb + SBUF + (uint32_t)(n & 1) * BSTR;
        CPA16(B2 + KH + kdst, kga + (size_t)n * 4096);
        CPA16(B2 + KL + kdst, kgb + (size_t)n * 4096);
        CPA16(B2 + VH + kdst, vga + (size_t)n * 4096);
        CPA16(B2 + VL + kdst, vgb + (size_t)n * 4096);
        CPC();
    };

    issueKV(0);

#pragma unroll
    for (int u = 0; u < 2; u++) {
        int lin = tid + u * 256;
        int row = lin >> 2, seg = lin & 3;
        size_t src = ((size_t)bx * 512 + mtile * 128 + row) * 32 + seg * 8;
        st128(sb + SQH + row * 80 + seg * 16, *(const uint4*)(g_qh + src));
        st128(sb + SQL + row * 80 + seg * 16, *(const uint4*)(g_ql + src));
    }
    CPW0();
    __syncthreads();

    uint32_t aoff = (uint32_t)(((lane & 7) + ((lane >> 3) & 1) * 8) * 80 + (lane >> 4) * 16);
    uint32_t boff = (uint32_t)(((lane & 7) + (lane >> 4) * 8) * 80 + ((lane >> 3) & 1) * 16);
    uint32_t qh[2][4], ql[2][4];
#pragma unroll
    for (int ks = 0; ks < 2; ks++) {
        ldmx4(qh[ks], sb + SQH + (uint32_t)(wid * 16) * 80 + aoff + ks * 32);
        ldmx4(ql[ks], sb + SQL + (uint32_t)(wid * 16) * 80 + aoff + ks * 32);
    }

    float oacc[4][4];
#pragma unroll
    for (int a = 0; a < 4; a++)
#pragma unroll
        for (int b = 0; b < 4; b++) oacc[a][b] = 0.f;
    float rs0 = 0.f, rs1 = 0.f;
    int quad = lane >> 2, tg = lane & 3;
    int ib = mtile * 8 + wid;
    const __nv_bfloat16* bf = g_bfrag + ((((size_t)cfg * 8 + h) * 32 + ib) * 64) * 128;

#pragma unroll 1
    for (int jt = 0; jt < 8; jt++) {
        if (jt < 7) issueKV(jt + 1);
        uint32_t B = sb + SBUF + (uint32_t)(jt & 1) * BSTR;

        float sacc[8][4];
#pragma unroll
        for (int a = 0; a < 8; a++)
#pragma unroll
            for (int b = 0; b < 4; b++) sacc[a][b] = 0.f;
#pragma unroll
        for (int ks = 0; ks < 2; ks++)
#pragma unroll
            for (int p = 0; p < 4; p++) {
                uint32_t bh[4], bl[4];
                ldmx4(bh, B + KH + (uint32_t)(p * 16) * 80 + boff + ks * 32);
                ldmx4(bl, B + KL + (uint32_t)(p * 16) * 80 + boff + ks * 32);
#pragma unroll
                for (int n2 = 0; n2 < 2; n2++) {
                    mma16816(sacc[2 * p + n2], qh[ks], &bh[n2 * 2]);
                    mma16816(sacc[2 * p + n2], qh[ks], &bl[n2 * 2]);
                    mma16816(sacc[2 * p + n2], ql[ks], &bh[n2 * 2]);
                }
            }

        uint32_t aP[4][4];
#pragma unroll
        for (int nt = 0; nt < 8; nt++) {
            const uint32_t* bp = (const uint32_t*)(bf + (size_t)(jt * 8 + nt) * 128);
            __nv_bfloat162 bb01 = *(const __nv_bfloat162*)&bp[quad * 4 + tg];
            __nv_bfloat162 bb23 = *(const __nv_bfloat162*)&bp[32 + quad * 4 + tg];
            float2 b01 = __bfloat1622float2(bb01);
            float2 b23 = __bfloat1622float2(bb23);
            float p0 = exp2f(sacc[nt][0] + b01.x);
            float p1 = exp2f(sacc[nt][1] + b01.y);
            float p2 = exp2f(sacc[nt][2] + b23.x);
            float p3 = exp2f(sacc[nt][3] + b23.y);
            rs0 += p0 + p1;
            rs1 += p2 + p3;
            int kt = nt >> 1, o = (nt & 1) * 2;
            aP[kt][o]     = pack_f16x2(p0, p1);
            aP[kt][o + 1] = pack_f16x2(p2, p3);
        }

        // PV (fp16): V via ldmatrix.trans from [tok][32] tiles
#pragma unroll
        for (int kt = 0; kt < 4; kt++) {
            uint32_t vh[4][2], vl[4][2];
#pragma unroll
            for (int dp = 0; dp < 2; dp++) {
                uint32_t t4[4];
                ldmx4t(t4, B + VH + (uint32_t)(kt * 16) * 80 + aoff + dp * 32);
                vh[dp * 2][0] = t4[0]; vh[dp * 2][1] = t4[1];
                vh[dp * 2 + 1][0] = t4[2]; vh[dp * 2 + 1][1] = t4[3];
                ldmx4t(t4, B + VL + (uint32_t)(kt * 16) * 80 + aoff + dp * 32);
                vl[dp * 2][0] = t4[0]; vl[dp * 2][1] = t4[1];
                vl[dp * 2 + 1][0] = t4[2]; vl[dp * 2 + 1][1] = t4[3];
            }
#pragma unroll
            for (int nb = 0; nb < 4; nb++) {
                mma16816h(oacc[nb], aP[kt], vh[nb]);
                mma16816h(oacc[nb], aP[kt], vl[nb]);
            }
        }

        if (jt < 7) {
            CPW0();
            __syncthreads();
        }
    }

    rs0 += __shfl_xor_sync(0xFFFFFFFF, rs0, 1);
    rs0 += __shfl_xor_sync(0xFFFFFFFF, rs0, 2);
    rs1 += __shfl_xor_sync(0xFFFFFFFF, rs1, 1);
    rs1 += __shfl_xor_sync(0xFFFFFFFF, rs1, 2);
    float inv0 = 1.f / rs0, inv1 = 1.f / rs1;
    int qtok = mtile * 128 + wid * 16 + quad;
    int t0 = w * 512 + qtok, t1 = t0 + 8;
#pragma unroll
    for (int nt = 0; nt < 4; nt++) {
        int c = h * 32 + nt * 8 + tg * 2;
        uint32_t hi, lo;
        split2(oacc[nt][0] * inv0, oacc[nt][1] * inv0, hi, lo);
        __nv_bfloat16* d0 = g_acat + (size_t)t0 * KCAT2 + c;
        *(uint32_t*)d0         = hi;
        *(uint32_t*)(d0 + 256) = lo;
        split2(oacc[nt][2] * inv1, oacc[nt][3] * inv1, hi, lo);
        __nv_bfloat16* d1 = g_acat + (size_t)t1 * KCAT2 + c;
        *(uint32_t*)d1         = hi;
        *(uint32_t*)(d1 + 256) = lo;
    }
}

extern "C" void kernel_launch(void* const* d_in, const int* in_sizes, int n_in,
                              void* d_out, int out_size) {
    const float* x      = (const float*)d_in[0];
    const float* qkv_w  = (const float*)d_in[1];
    const float* qkv_b  = (const float*)d_in[2];
    const float* proj_w = (const float*)d_in[3];
    const float* proj_b = (const float*)d_in[4];
    const float* rpb    = (const float*)d_in[5];
    float* out = (float*)d_out;

    cudaFuncSetAttribute(hmma_gemm_kernel, cudaFuncAttributeMaxDynamicSharedMemorySize, 81920);
    cudaFuncSetAttribute(attn_mma_kernel, cudaFuncAttributeMaxDynamicSharedMemorySize, 61440);

    prep_tok_kernel<<<128, 256>>>();
    prep_bias_kernel<<<4096, 512>>>(rpb);
    conv_w_kernel<<<768, 32>>>(qkv_w);
    conv_a_kernel<<<4096, 256>>>(x);
    hmma_gemm_kernel<<<dim3(256, 6), 256, 81920>>>(qkv_b, nullptr, 0);
    conv_w_kernel<<<256, 32>>>(proj_w);
    attn_mma_kernel<<<2048, 256, 61440>>>();
    hmma_gemm_kernel<<<dim3(256, 2), 256, 81920>>>(proj_b, out, 1);
}

// round 16
// speedup vs baseline: 1.1969x; 1.0496x over previous
#include <cuda_runtime.h>
#include <cuda_bf16.h>
#include <cuda_fp16.h>
#include <math.h>
#include <stdint.h>

#define NWIN 64
#define NTOK 512
#define NHEAD 8
#define HDIM 32
#define CDIM 256
#define KCAT2 512           // [hi(256) | lo(256)]
#define MTOT 32768

#define LOG2E 1.4426950408889634f
#define QSCALE (0.17677669529663687f * 1.4426950408889634f)

__device__ __half g_qf[(size_t)512 * 512 * 32];          // fp16 q (single)
__device__ __half g_kh[(size_t)512 * 512 * 32];          // fp16 k hi
__device__ __half g_kl[(size_t)512 * 512 * 32];          // fp16 k lo
__device__ __half g_vh[(size_t)512 * 512 * 32];          // fp16 V hi
__device__ __half g_vl[(size_t)512 * 512 * 32];          // fp16 V lo
__device__ __nv_bfloat16 g_bfrag[(size_t)8 * 8 * 32 * 64 * 128];
__device__ int   g_tokoff[NWIN * NTOK];
__device__ __nv_bfloat16 g_acat[(size_t)MTOT * KCAT2];
__device__ __nv_bfloat16 g_bcat[(size_t)768 * KCAT2];

__device__ __forceinline__ uint32_t smem_u32(const void* p) {
    uint32_t a;
    asm("{ .reg .u64 t; cvta.to.shared.u64 t, %1; cvt.u32.u64 %0, t; }" : "=r"(a) : "l"(p));
    return a;
}
__device__ __forceinline__ void ldmx4(uint32_t* r, uint32_t addr) {
    asm volatile("ldmatrix.sync.aligned.m8n8.x4.shared.b16 {%0,%1,%2,%3}, [%4];"
                 : "=r"(r[0]), "=r"(r[1]), "=r"(r[2]), "=r"(r[3]) : "r"(addr));
}
__device__ __forceinline__ void ldmx4t(uint32_t* r, uint32_t addr) {
    asm volatile("ldmatrix.sync.aligned.m8n8.x4.trans.shared.b16 {%0,%1,%2,%3}, [%4];"
                 : "=r"(r[0]), "=r"(r[1]), "=r"(r[2]), "=r"(r[3]) : "r"(addr));
}
__device__ __forceinline__ void st128(uint32_t addr, uint4 v) {
    asm volatile("st.shared.v4.b32 [%0], {%1,%2,%3,%4};"
                 :: "r"(addr), "r"(v.x), "r"(v.y), "r"(v.z), "r"(v.w) : "memory");
}
__device__ __forceinline__ void mma16816(float* c, const uint32_t* a, const uint32_t* b) {
    asm volatile("mma.sync.aligned.m16n8k16.row.col.f32.bf16.bf16.f32 "
                 "{%0,%1,%2,%3}, {%4,%5,%6,%7}, {%8,%9}, {%0,%1,%2,%3};"
                 : "+f"(c[0]), "+f"(c[1]), "+f"(c[2]), "+f"(c[3])
                 : "r"(a[0]), "r"(a[1]), "r"(a[2]), "r"(a[3]), "r"(b[0]), "r"(b[1]));
}
__device__ __forceinline__ void mma16816h(float* c, const uint32_t* a, const uint32_t* b) {
    asm volatile("mma.sync.aligned.m16n8k16.row.col.f32.f16.f16.f32 "
                 "{%0,%1,%2,%3}, {%4,%5,%6,%7}, {%8,%9}, {%0,%1,%2,%3};"
                 : "+f"(c[0]), "+f"(c[1]), "+f"(c[2]), "+f"(c[3])
                 : "r"(a[0]), "r"(a[1]), "r"(a[2]), "r"(a[3]), "r"(b[0]), "r"(b[1]));
}
// RN bf16 split (conv, attention out epilogue)
__device__ __forceinline__ void split2(float f0, float f1, uint32_t& hi, uint32_t& lo) {
    __nv_bfloat16 h0 = __float2bfloat16(f0), h1 = __float2bfloat16(f1);
    __nv_bfloat16 l0 = __float2bfloat16(f0 - __bfloat162float(h0));
    __nv_bfloat16 l1 = __float2bfloat16(f1 - __bfloat162float(h1));
    uint16_t uh0 = *(uint16_t*)&h0, uh1 = *(uint16_t*)&h1;
    uint16_t ul0 = *(uint16_t*)&l0, ul1 = *(uint16_t*)&l1;
    hi = (uint32_t)uh0 | ((uint32_t)uh1 << 16);
    lo = (uint32_t)ul0 | ((uint32_t)ul1 << 16);
}
// RN fp16 split (k/v epilogue)
__device__ __forceinline__ void split2h(float f0, float f1, uint32_t& hi, uint32_t& lo) {
    __half h0 = __float2half_rn(f0), h1 = __float2half_rn(f1);
    __half l0 = __float2half_rn(f0 - __half2float(h0));
    __half l1 = __float2half_rn(f1 - __half2float(h1));
    uint16_t uh0 = *(uint16_t*)&h0, uh1 = *(uint16_t*)&h1;
    uint16_t ul0 = *(uint16_t*)&l0, ul1 = *(uint16_t*)&l1;
    hi = (uint32_t)uh0 | ((uint32_t)uh1 << 16);
    lo = (uint32_t)ul0 | ((uint32_t)ul1 << 16);
}
__device__ __forceinline__ uint32_t pack_f16x2(float f0, float f1) {
    uint32_t r;
    asm("cvt.rn.f16x2.f32 %0, %1, %2;" : "=r"(r) : "f"(f1), "f"(f0));
    return r;
}
#define CPA16(dst, src) \
    asm volatile("cp.async.cg.shared.global [%0], [%1], 16;" :: "r"(dst), "l"(src) : "memory")
#define CPC() asm volatile("cp.async.commit_group;" ::: "memory")
#define CPW0() asm volatile("cp.async.wait_group 0;" ::: "memory")

// ---------------------------------------------------------------------------
__global__ void prep_tok_kernel() {
    int gid = blockIdx.x * 256 + threadIdx.x;
    int w = gid >> 9, n = gid & 511;
    int wh = w >> 4, ww = (w >> 2) & 3, wd = w & 3;
    int ih = n >> 6, iw = (n >> 3) & 7, id = n & 7;
    int gh = (wh * 8 + ih + 4) & 31;
    int gw = (ww * 8 + iw + 4) & 31;
    int gd = (wd * 8 + id + 4) & 31;
    g_tokoff[gid] = ((gh * 32 + gw) * 32 + gd) * 256;
}

// ---------------------------------------------------------------------------
__global__ void __launch_bounds__(512) prep_bias_kernel(const float* __restrict__ rpb) {
    int cfg = blockIdx.x >> 9, i = blockIdx.x & 511;
    int h = threadIdx.x >> 6, jb = threadIdx.x & 63;
    int ch = (cfg >> 2) & 1, cw = (cfg >> 1) & 1, cd = cfg & 1;
    int i0 = i >> 6, i1 = (i >> 3) & 7, i2 = i & 7;
    int ri = (ch ? (i0 < 4 ? 1 : 2) : 0) * 9 + (cw ? (i1 < 4 ? 1 : 2) : 0) * 3
           + (cd ? (i2 < 4 ? 1 : 2) : 0);
    int ib = i >> 4, half = (i & 15) >> 3, row = i & 7;
    int j0 = jb >> 3, j1 = jb & 7;
    int rjb = (ch ? (j0 < 4 ? 1 : 2) : 0) * 9 + (cw ? (j1 < 4 ? 1 : 2) : 0) * 3;
    int idxb = (i0 - j0 + 7) * 225 + (i1 - j1 + 7) * 15;
    union { __nv_bfloat16 h8[8]; uint4 u; } O;
#pragma unroll
    for (int j2 = 0; j2 < 8; j2++) {
        int rj = rjb + (cd ? (j2 < 4 ? 1 : 2) : 0);
        int idx = idxb + (i2 - j2 + 7);
        float m = (ri == rj) ? 0.f : -100.f;
        O.h8[j2] = __float2bfloat16((rpb[idx * 8 + h] + m) * LOG2E);
    }
    size_t base = (((((size_t)cfg * 8 + h) * 32 + ib) * 64 + jb) * 128) + half * 64 + row * 8;
    *(uint4*)(g_bfrag + base) = O.u;
}

// ---------------------------------------------------------------------------
__global__ void conv_a_kernel(const float* __restrict__ src) {
    int row = blockIdx.x * 8 + (threadIdx.x >> 5);
    int c8 = (threadIdx.x & 31) * 8;
    const float* sp = src + g_tokoff[row];
    float4 v0 = *(const float4*)(sp + c8);
    float4 v1 = *(const float4*)(sp + c8 + 4);
    float f[8] = {v0.x, v0.y, v0.z, v0.w, v1.x, v1.y, v1.z, v1.w};
    union { __nv_bfloat16 h[8]; uint4 u; } H, L;
#pragma unroll
    for (int i = 0; i < 8; i++) {
        H.h[i] = __float2bfloat16(f[i]);
        L.h[i] = __float2bfloat16(f[i] - __bfloat162float(H.h[i]));
    }
    __nv_bfloat16* dst = g_acat + (size_t)row * KCAT2;
    *(uint4*)(dst + c8)       = H.u;
    *(uint4*)(dst + 256 + c8) = L.u;
}

__global__ void conv_w_kernel(const float* __restrict__ W) {
    int row = blockIdx.x;
    int c8 = threadIdx.x * 8;
    const float* sp = W + (size_t)row * 256 + c8;
    float4 v0 = *(const float4*)(sp);
    float4 v1 = *(const float4*)(sp + 4);
    float f[8] = {v0.x, v0.y, v0.z, v0.w, v1.x, v1.y, v1.z, v1.w};
    union { __nv_bfloat16 h[8]; uint4 u; } H, L;
#pragma unroll
    for (int i = 0; i < 8; i++) {
        H.h[i] = __float2bfloat16(f[i]);
        L.h[i] = __float2bfloat16(f[i] - __bfloat162float(H.h[i]));
    }
    __nv_bfloat16* dst = g_bcat + (size_t)row * KCAT2;
    *(uint4*)(dst + c8)       = H.u;
    *(uint4*)(dst + 256 + c8) = L.u;
}

// ---------------------------------------------------------------------------
// HMMA GEMM (R12 superchunk mainloop; epilogue: q single fp16, k/v fp16 hi/lo).
// ---------------------------------------------------------------------------
__global__ void __launch_bounds__(256, 2) hmma_gemm_kernel(const float* __restrict__ bias,
                                                           float* __restrict__ out, int mode) {
    extern __shared__ __align__(16) char smem[];
    uint32_t sbase = smem_u32(smem);
    int tid = threadIdx.x;
    int lane = tid & 31, wid = tid >> 5;
    int wm = wid & 3, wn = wid >> 2;
    int m0 = blockIdx.x * 128, n0 = blockIdx.y * 128;

    int lr = tid >> 1, lh = tid & 1;
    const char* Arow = (const char*)g_acat + (size_t)(m0 + lr) * 1024;
    const char* Brow = (const char*)g_bcat + (size_t)(n0 + lr) * 1024;
    uint32_t stoff = (uint32_t)(lr * 80 + lh * 32);

    const uint32_t AH = 0, AL = 10240, BH = 20480, BL = 30720;

    auto issue = [&](int n) {
        uint32_t st = sbase + (uint32_t)(n & 1) * 40960u;
        int so = n * 64 + lh * 32;
#pragma unroll
        for (int i = 0; i < 2; i++) {
            CPA16(st + AH + stoff + i * 16, Arow + so + i * 16);
            CPA16(st + AL + stoff + i * 16, Arow + 512 + so + i * 16);
            CPA16(st + BH + stoff + i * 16, Brow + so + i * 16);
            CPA16(st + BL + stoff + i * 16, Brow + 512 + so + i * 16);
        }
        CPC();
    };

    uint32_t aoff = (uint32_t)((((lane & 7) + ((lane >> 3) & 1) * 8) * 80) + (lane >> 4) * 16);
    uint32_t boff = (uint32_t)((((lane & 7) + (lane >> 4) * 8) * 80) + ((lane >> 3) & 1) * 16);

    float acc[2][8][4];
#pragma unroll
    for (int a = 0; a < 2; a++)
#pragma unroll
        for (int b = 0; b < 8; b++)
#pragma unroll
            for (int c = 0; c < 4; c++) acc[a][b][c] = 0.f;

    issue(0);
    CPW0();
    __syncthreads();

#pragma unroll 1
    for (int c = 0; c < 8; c++) {
        if (c < 7) issue(c + 1);

        uint32_t st = sbase + (uint32_t)(c & 1) * 40960u;
        uint32_t AHw = st + AH + (uint32_t)(wm * 32) * 80u + aoff;
        uint32_t ALw = st + AL + (uint32_t)(wm * 32) * 80u + aoff;
        uint32_t BHw = st + BH + (uint32_t)(wn * 64) * 80u + boff;
        uint32_t BLw = st + BL + (uint32_t)(wn * 64) * 80u + boff;
#pragma unroll
        for (int ks = 0; ks < 2; ks++) {
            uint32_t ah[2][4], al[2][4];
#pragma unroll
            for (int mt = 0; mt < 2; mt++) {
                ldmx4(ah[mt], AHw + (uint32_t)(mt * 16) * 80u + ks * 32u);
                ldmx4(al[mt], ALw + (uint32_t)(mt * 16) * 80u + ks * 32u);
            }
            uint32_t bh[8][2];
#pragma unroll
            for (int p = 0; p < 4; p++) {
                uint32_t t4[4];
                ldmx4(t4, BHw + (uint32_t)(p * 16) * 80u + ks * 32u);
                bh[2 * p][0] = t4[0]; bh[2 * p][1] = t4[1];
                bh[2 * p + 1][0] = t4[2]; bh[2 * p + 1][1] = t4[3];
            }
#pragma unroll
            for (int mt = 0; mt < 2; mt++)
#pragma unroll
                for (int nt = 0; nt < 8; nt++) {
                    mma16816(acc[mt][nt], ah[mt], bh[nt]);
                    mma16816(acc[mt][nt], al[mt], bh[nt]);
                }
            uint32_t bl[8][2];
#pragma unroll
            for (int p = 0; p < 4; p++) {
                uint32_t t4[4];
                ldmx4(t4, BLw + (uint32_t)(p * 16) * 80u + ks * 32u);
                bl[2 * p][0] = t4[0]; bl[2 * p][1] = t4[1];
                bl[2 * p + 1][0] = t4[2]; bl[2 * p + 1][1] = t4[3];
            }
#pragma unroll
            for (int mt = 0; mt < 2; mt++)
#pragma unroll
                for (int nt = 0; nt < 8; nt++)
                    mma16816(acc[mt][nt], ah[mt], bl[nt]);
        }
        if (c < 7) {
            CPW0();
            __syncthreads();
        }
    }

    int quad = lane >> 2, tg = lane & 3;
#pragma unroll
    for (int mt = 0; mt < 2; mt++) {
        int rbase = m0 + wm * 32 + mt * 16 + quad;
#pragma unroll
        for (int nt = 0; nt < 8; nt++) {
            int col = n0 + wn * 64 + nt * 8 + tg * 2;
            float2 bb = *(const float2*)(bias + col);
            if (mode == 0) {
                int sec = n0 >> 8;
                float sc = (sec == 0) ? QSCALE : 1.0f;
                int head = (col & 255) >> 5, dd = col & 31;
#pragma unroll
                for (int hf = 0; hf < 2; hf++) {
                    int rr = rbase + hf * 8;
                    int w = rr >> 9, nn = rr & 511;
                    size_t bxi = (size_t)(w * 8 + head);
                    size_t eoff = (bxi * 512 + nn) * 32 + dd;
                    float f0 = (acc[mt][nt][hf * 2 + 0] + bb.x) * sc;
                    float f1 = (acc[mt][nt][hf * 2 + 1] + bb.y) * sc;
                    if (sec == 0) {
                        *(uint32_t*)(g_qf + eoff) = pack_f16x2(f0, f1);
                    } else {
                        uint32_t hi, lo;
                        split2h(f0, f1, hi, lo);
                        *(uint32_t*)((sec == 1 ? g_kh : g_vh) + eoff) = hi;
                        *(uint32_t*)((sec == 1 ? g_kl : g_vl) + eoff) = lo;
                    }
                }
            } else {
#pragma unroll
                for (int hf = 0; hf < 2; hf++) {
                    int rr = rbase + hf * 8;
                    int off = g_tokoff[rr] + col;
                    float2 o;
                    o.x = acc[mt][nt][hf * 2 + 0] + bb.x;
                    o.y = acc[mt][nt][hf * 2 + 1] + bb.y;
                    *(float2*)(out + off) = o;
                }
            }
        }
    }
}

// ---------------------------------------------------------------------------
// HMMA attention: QK fp16 2-term (q single, k hi/lo); PV fp16 single-P 2-term.
// smem: Qf 10240 | 2 x (KH KL VH VL 5120 each = 20480). Total 51200 B.
// ---------------------------------------------------------------------------
__global__ void __launch_bounds__(256, 2) attn_mma_kernel() {
    extern __shared__ __align__(16) char sm[];
    uint32_t sb = smem_u32(sm);
    const int tid = threadIdx.x, lane = tid & 31, wid = tid >> 5;
    int bx = blockIdx.x >> 2, mtile = blockIdx.x & 3;
    int w = bx >> 3, h = bx & 7;
    int cfg = (((w >> 4) == 3) ? 4 : 0) | ((((w >> 2) & 3) == 3) ? 2 : 0) | (((w & 3) == 3) ? 1 : 0);

    const uint32_t SQF = 0, SBUF = 10240, BSTR = 20480;
    const uint32_t KH = 0, KL = 5120, VH = 10240, VL = 15360;

    int row_k = tid >> 2, seg_k = tid & 3;
    const char* kga = (const char*)g_kh + (size_t)bx * 32768 + row_k * 64 + seg_k * 16;
    const char* kgb = (const char*)g_kl + (size_t)bx * 32768 + row_k * 64 + seg_k * 16;
    const char* vga = (const char*)g_vh + (size_t)bx * 32768 + row_k * 64 + seg_k * 16;
    const char* vgb = (const char*)g_vl + (size_t)bx * 32768 + row_k * 64 + seg_k * 16;
    uint32_t kdst = row_k * 80 + seg_k * 16;

    auto issueKV = [&](int n) {
        uint32_t B2 = sb + SBUF + (uint32_t)(n & 1) * BSTR;
        CPA16(B2 + KH + kdst, kga + (size_t)n * 4096);
        CPA16(B2 + KL + kdst, kgb + (size_t)n * 4096);
        CPA16(B2 + VH + kdst, vga + (size_t)n * 4096);
        CPA16(B2 + VL + kdst, vgb + (size_t)n * 4096);
        CPC();
    };

    issueKV(0);

    // stage Q (128 rows x 64 B fp16, stride 80): 2 chunks per thread
#pragma unroll
    for (int u = 0; u < 2; u++) {
        int lin = tid + u * 256;
        int row = lin >> 2, seg = lin & 3;
        size_t src = ((size_t)bx * 512 + mtile * 128 + row) * 32 + seg * 8;
        st128(sb + SQF + row * 80 + seg * 16, *(const uint4*)(g_qf + src));
    }
    CPW0();
    __syncthreads();

    uint32_t aoff = (uint32_t)(((lane & 7) + ((lane >> 3) & 1) * 8) * 80 + (lane >> 4) * 16);
    uint32_t boff = (uint32_t)(((lane & 7) + (lane >> 4) * 8) * 80 + ((lane >> 3) & 1) * 16);
    uint32_t qf[2][4];
#pragma unroll
    for (int ks = 0; ks < 2; ks++)
        ldmx4(qf[ks], sb + SQF + (uint32_t)(wid * 16) * 80 + aoff + ks * 32);

    float oacc[4][4];
#pragma unroll
    for (int a = 0; a < 4; a++)
#pragma unroll
        for (int b = 0; b < 4; b++) oacc[a][b] = 0.f;
    float rs0 = 0.f, rs1 = 0.f;
    int quad = lane >> 2, tg = lane & 3;
    int ib = mtile * 8 + wid;
    const __nv_bfloat16* bf = g_bfrag + ((((size_t)cfg * 8 + h) * 32 + ib) * 64) * 128;

#pragma unroll 1
    for (int jt = 0; jt < 8; jt++) {
        if (jt < 7) issueKV(jt + 1);
        uint32_t B = sb + SBUF + (uint32_t)(jt & 1) * BSTR;

        float sacc[8][4];
#pragma unroll
        for (int a = 0; a < 8; a++)
#pragma unroll
            for (int b = 0; b < 4; b++) sacc[a][b] = 0.f;
#pragma unroll
        for (int ks = 0; ks < 2; ks++)
#pragma unroll
            for (int p = 0; p < 4; p++) {
                uint32_t bh[4], bl[4];
                ldmx4(bh, B + KH + (uint32_t)(p * 16) * 80 + boff + ks * 32);
                ldmx4(bl, B + KL + (uint32_t)(p * 16) * 80 + boff + ks * 32);
#pragma unroll
                for (int n2 = 0; n2 < 2; n2++) {
                    mma16816h(sacc[2 * p + n2], qf[ks], &bh[n2 * 2]);
                    mma16816h(sacc[2 * p + n2], qf[ks], &bl[n2 * 2]);
                }
            }

        uint32_t aP[4][4];
#pragma unroll
        for (int nt = 0; nt < 8; nt++) {
            const uint32_t* bp = (const uint32_t*)(bf + (size_t)(jt * 8 + nt) * 128);
            __nv_bfloat162 bb01 = *(const __nv_bfloat162*)&bp[quad * 4 + tg];
            __nv_bfloat162 bb23 = *(const __nv_bfloat162*)&bp[32 + quad * 4 + tg];
            float2 b01 = __bfloat1622float2(bb01);
            float2 b23 = __bfloat1622float2(bb23);
            float p0 = exp2f(sacc[nt][0] + b01.x);
            float p1 = exp2f(sacc[nt][1] + b01.y);
            float p2 = exp2f(sacc[nt][2] + b23.x);
            float p3 = exp2f(sacc[nt][3] + b23.y);
            rs0 += p0 + p1;
            rs1 += p2 + p3;
            int kt = nt >> 1, o = (nt & 1) * 2;
            aP[kt][o]     = pack_f16x2(p0, p1);
            aP[kt][o + 1] = pack_f16x2(p2, p3);
        }

        // PV (fp16): V via ldmatrix.trans from [tok][32] tiles
#pragma unroll
        for (int kt = 0; kt < 4; kt++) {
            uint32_t vh[4][2], vl[4][2];
#pragma unroll
            for (int dp = 0; dp < 2; dp++) {
                uint32_t t4[4];
                ldmx4t(t4, B + VH + (uint32_t)(kt * 16) * 80 + aoff + dp * 32);
                vh[dp * 2][0] = t4[0]; vh[dp * 2][1] = t4[1];
                vh[dp * 2 + 1][0] = t4[2]; vh[dp * 2 + 1][1] = t4[3];
                ldmx4t(t4, B + VL + (uint32_t)(kt * 16) * 80 + aoff + dp * 32);
                vl[dp * 2][0] = t4[0]; vl[dp * 2][1] = t4[1];
                vl[dp * 2 + 1][0] = t4[2]; vl[dp * 2 + 1][1] = t4[3];
            }
#pragma unroll
            for (int nb = 0; nb < 4; nb++) {
                mma16816h(oacc[nb], aP[kt], vh[nb]);
                mma16816h(oacc[nb], aP[kt], vl[nb]);
            }
        }

        if (jt < 7) {
            CPW0();
            __syncthreads();
        }
    }

    rs0 += __shfl_xor_sync(0xFFFFFFFF, rs0, 1);
    rs0 += __shfl_xor_sync(0xFFFFFFFF, rs0, 2);
    rs1 += __shfl_xor_sync(0xFFFFFFFF, rs1, 1);
    rs1 += __shfl_xor_sync(0xFFFFFFFF, rs1, 2);
    float inv0 = 1.f / rs0, inv1 = 1.f / rs1;
    int qtok = mtile * 128 + wid * 16 + quad;
    int t0 = w * 512 + qtok, t1 = t0 + 8;
#pragma unroll
    for (int nt = 0; nt < 4; nt++) {
        int c = h * 32 + nt * 8 + tg * 2;
        uint32_t hi, lo;
        split2(oacc[nt][0] * inv0, oacc[nt][1] * inv0, hi, lo);
        __nv_bfloat16* d0 = g_acat + (size_t)t0 * KCAT2 + c;
        *(uint32_t*)d0         = hi;
        *(uint32_t*)(d0 + 256) = lo;
        split2(oacc[nt][2] * inv1, oacc[nt][3] * inv1, hi, lo);
        __nv_bfloat16* d1 = g_acat + (size_t)t1 * KCAT2 + c;
        *(uint32_t*)d1         = hi;
        *(uint32_t*)(d1 + 256) = lo;
    }
}

extern "C" void kernel_launch(void* const* d_in, const int* in_sizes, int n_in,
                              void* d_out, int out_size) {
    const float* x      = (const float*)d_in[0];
    const float* qkv_w  = (const float*)d_in[1];
    const float* qkv_b  = (const float*)d_in[2];
    const float* proj_w = (const float*)d_in[3];
    const float* proj_b = (const float*)d_in[4];
    const float* rpb    = (const float*)d_in[5];
    float* out = (float*)d_out;

    cudaFuncSetAttribute(hmma_gemm_kernel, cudaFuncAttributeMaxDynamicSharedMemorySize, 81920);
    cudaFuncSetAttribute(attn_mma_kernel, cudaFuncAttributeMaxDynamicSharedMemorySize, 51200);

    prep_tok_kernel<<<128, 256>>>();
    prep_bias_kernel<<<4096, 512>>>(rpb);
    conv_w_kernel<<<768, 32>>>(qkv_w);
    conv_a_kernel<<<4096, 256>>>(x);
    hmma_gemm_kernel<<<dim3(256, 6), 256, 81920>>>(qkv_b, nullptr, 0);
    conv_w_kernel<<<256, 32>>>(proj_w);
    attn_mma_kernel<<<2048, 256, 51200>>>();
    hmma_gemm_kernel<<<dim3(256, 2), 256, 81920>>>(proj_b, out, 1);
}

// round 17
// speedup vs baseline: 1.4032x; 1.1724x over previous
#include <cuda_runtime.h>
#include <cuda_bf16.h>
#include <cuda_fp16.h>
#include <math.h>
#include <stdint.h>

#define NWIN 64
#define NTOK 512
#define NHEAD 8
#define HDIM 32
#define CDIM 256
#define MTOT 32768

#define LOG2E 1.4426950408889634f
#define QSCALE (0.17677669529663687f * 1.4426950408889634f)

__device__ __half g_qf[(size_t)512 * 512 * 32];          // fp16 q (single)
__device__ __half g_kh[(size_t)512 * 512 * 32];          // fp16 k hi
__device__ __half g_kl[(size_t)512 * 512 * 32];          // fp16 k lo
__device__ __half g_vh[(size_t)512 * 512 * 32];          // fp16 V hi
__device__ __half g_vl[(size_t)512 * 512 * 32];          // fp16 V lo
__device__ __nv_bfloat16 g_bfrag[(size_t)8 * 8 * 32 * 64 * 128];
__device__ int   g_tokoff[NWIN * NTOK];
__device__ __half g_acat[(size_t)MTOT * 256];            // fp16 A (single)
__device__ __half g_bcat[(size_t)768 * 512];             // fp16 W [hi(256)|lo(256)]

__device__ __forceinline__ uint32_t smem_u32(const void* p) {
    uint32_t a;
    asm("{ .reg .u64 t; cvta.to.shared.u64 t, %1; cvt.u32.u64 %0, t; }" : "=r"(a) : "l"(p));
    return a;
}
__device__ __forceinline__ void ldmx4(uint32_t* r, uint32_t addr) {
    asm volatile("ldmatrix.sync.aligned.m8n8.x4.shared.b16 {%0,%1,%2,%3}, [%4];"
                 : "=r"(r[0]), "=r"(r[1]), "=r"(r[2]), "=r"(r[3]) : "r"(addr));
}
__device__ __forceinline__ void ldmx4t(uint32_t* r, uint32_t addr) {
    asm volatile("ldmatrix.sync.aligned.m8n8.x4.trans.shared.b16 {%0,%1,%2,%3}, [%4];"
                 : "=r"(r[0]), "=r"(r[1]), "=r"(r[2]), "=r"(r[3]) : "r"(addr));
}
__device__ __forceinline__ void st128(uint32_t addr, uint4 v) {
    asm volatile("st.shared.v4.b32 [%0], {%1,%2,%3,%4};"
                 :: "r"(addr), "r"(v.x), "r"(v.y), "r"(v.z), "r"(v.w) : "memory");
}
__device__ __forceinline__ void mma16816h(float* c, const uint32_t* a, const uint32_t* b) {
    asm volatile("mma.sync.aligned.m16n8k16.row.col.f32.f16.f16.f32 "
                 "{%0,%1,%2,%3}, {%4,%5,%6,%7}, {%8,%9}, {%0,%1,%2,%3};"
                 : "+f"(c[0]), "+f"(c[1]), "+f"(c[2]), "+f"(c[3])
                 : "r"(a[0]), "r"(a[1]), "r"(a[2]), "r"(a[3]), "r"(b[0]), "r"(b[1]));
}
// RN fp16 split
__device__ __forceinline__ void split2h(float f0, float f1, uint32_t& hi, uint32_t& lo) {
    __half h0 = __float2half_rn(f0), h1 = __float2half_rn(f1);
    __half l0 = __float2half_rn(f0 - __half2float(h0));
    __half l1 = __float2half_rn(f1 - __half2float(h1));
    uint16_t uh0 = *(uint16_t*)&h0, uh1 = *(uint16_t*)&h1;
    uint16_t ul0 = *(uint16_t*)&l0, ul1 = *(uint16_t*)&l1;
    hi = (uint32_t)uh0 | ((uint32_t)uh1 << 16);
    lo = (uint32_t)ul0 | ((uint32_t)ul1 << 16);
}
__device__ __forceinline__ uint32_t pack_f16x2(float f0, float f1) {
    uint32_t r;
    asm("cvt.rn.f16x2.f32 %0, %1, %2;" : "=r"(r) : "f"(f1), "f"(f0));
    return r;
}
#define CPA16(dst, src) \
    asm volatile("cp.async.cg.shared.global [%0], [%1], 16;" :: "r"(dst), "l"(src) : "memory")
#define CPC() asm volatile("cp.async.commit_group;" ::: "memory")
#define CPW0() asm volatile("cp.async.wait_group 0;" ::: "memory")

// ---------------------------------------------------------------------------
__global__ void prep_tok_kernel() {
    int gid = blockIdx.x * 256 + threadIdx.x;
    int w = gid >> 9, n = gid & 511;
    int wh = w >> 4, ww = (w >> 2) & 3, wd = w & 3;
    int ih = n >> 6, iw = (n >> 3) & 7, id = n & 7;
    int gh = (wh * 8 + ih + 4) & 31;
    int gw = (ww * 8 + iw + 4) & 31;
    int gd = (wd * 8 + id + 4) & 31;
    g_tokoff[gid] = ((gh * 32 + gw) * 32 + gd) * 256;
}

// ---------------------------------------------------------------------------
__global__ void __launch_bounds__(512) prep_bias_kernel(const float* __restrict__ rpb) {
    int cfg = blockIdx.x >> 9, i = blockIdx.x & 511;
    int h = threadIdx.x >> 6, jb = threadIdx.x & 63;
    int ch = (cfg >> 2) & 1, cw = (cfg >> 1) & 1, cd = cfg & 1;
    int i0 = i >> 6, i1 = (i >> 3) & 7, i2 = i & 7;
    int ri = (ch ? (i0 < 4 ? 1 : 2) : 0) * 9 + (cw ? (i1 < 4 ? 1 : 2) : 0) * 3
           + (cd ? (i2 < 4 ? 1 : 2) : 0);
    int ib = i >> 4, half = (i & 15) >> 3, row = i & 7;
    int j0 = jb >> 3, j1 = jb & 7;
    int rjb = (ch ? (j0 < 4 ? 1 : 2) : 0) * 9 + (cw ? (j1 < 4 ? 1 : 2) : 0) * 3;
    int idxb = (i0 - j0 + 7) * 225 + (i1 - j1 + 7) * 15;
    union { __nv_bfloat16 h8[8]; uint4 u; } O;
#pragma unroll
    for (int j2 = 0; j2 < 8; j2++) {
        int rj = rjb + (cd ? (j2 < 4 ? 1 : 2) : 0);
        int idx = idxb + (i2 - j2 + 7);
        float m = (ri == rj) ? 0.f : -100.f;
        O.h8[j2] = __float2bfloat16((rpb[idx * 8 + h] + m) * LOG2E);
    }
    size_t base = (((((size_t)cfg * 8 + h) * 32 + ib) * 64 + jb) * 128) + half * 64 + row * 8;
    *(uint4*)(g_bfrag + base) = O.u;
}

// ---------------------------------------------------------------------------
// conv_a: fp32 -> single fp16 (x gathered via tokoff).
// ---------------------------------------------------------------------------
__global__ void conv_a_kernel(const float* __restrict__ src) {
    int row = blockIdx.x * 8 + (threadIdx.x >> 5);
    int c8 = (threadIdx.x & 31) * 8;
    const float* sp = src + g_tokoff[row];
    float4 v0 = *(const float4*)(sp + c8);
    float4 v1 = *(const float4*)(sp + c8 + 4);
    float f[8] = {v0.x, v0.y, v0.z, v0.w, v1.x, v1.y, v1.z, v1.w};
    union { __half h[8]; uint4 u; } H;
#pragma unroll
    for (int i = 0; i < 8; i++) H.h[i] = __float2half_rn(f[i]);
    *(uint4*)(g_acat + (size_t)row * 256 + c8) = H.u;
}

// conv_w: fp32 -> fp16 hi|lo (512 wide).
__global__ void conv_w_kernel(const float* __restrict__ W) {
    int row = blockIdx.x;
    int c8 = threadIdx.x * 8;
    const float* sp = W + (size_t)row * 256 + c8;
    float4 v0 = *(const float4*)(sp);
    float4 v1 = *(const float4*)(sp + 4);
    float f[8] = {v0.x, v0.y, v0.z, v0.w, v1.x, v1.y, v1.z, v1.w};
    union { __half h[8]; uint4 u; } H, L;
#pragma unroll
    for (int i = 0; i < 8; i++) {
        H.h[i] = __float2half_rn(f[i]);
        L.h[i] = __float2half_rn(f[i] - __half2float(H.h[i]));
    }
    __half* dst = g_bcat + (size_t)row * 512;
    *(uint4*)(dst + c8)       = H.u;
    *(uint4*)(dst + 256 + c8) = L.u;
}

// ---------------------------------------------------------------------------
// HMMA GEMM fp16 2-term: D = Af*Wh + Af*Wl. K=256 in 8 superchunks of 32.
// Stage: AF 10240 | BH 10240 | BL 10240 = 30720; double buffer 61440.
// ---------------------------------------------------------------------------
__global__ void __launch_bounds__(256, 2) hmma_gemm_kernel(const float* __restrict__ bias,
                                                           float* __restrict__ out, int mode) {
    extern __shared__ __align__(16) char smem[];
    uint32_t sbase = smem_u32(smem);
    int tid = threadIdx.x;
    int lane = tid & 31, wid = tid >> 5;
    int wm = wid & 3, wn = wid >> 2;
    int m0 = blockIdx.x * 128, n0 = blockIdx.y * 128;

    int lr = tid >> 1, lh = tid & 1;
    const char* Arow = (const char*)g_acat + (size_t)(m0 + lr) * 512;
    const char* Brow = (const char*)g_bcat + (size_t)(n0 + lr) * 1024;
    uint32_t stoff = (uint32_t)(lr * 80 + lh * 32);

    const uint32_t AF = 0, BH = 10240, BL = 20480;

    auto issue = [&](int n) {
        uint32_t st = sbase + (uint32_t)(n & 1) * 30720u;
        int so = n * 64 + lh * 32;
#pragma unroll
        for (int i = 0; i < 2; i++) {
            CPA16(st + AF + stoff + i * 16, Arow + so + i * 16);
            CPA16(st + BH + stoff + i * 16, Brow + so + i * 16);
            CPA16(st + BL + stoff + i * 16, Brow + 512 + so + i * 16);
        }
        CPC();
    };

    uint32_t aoff = (uint32_t)((((lane & 7) + ((lane >> 3) & 1) * 8) * 80) + (lane >> 4) * 16);
    uint32_t boff = (uint32_t)((((lane & 7) + (lane >> 4) * 8) * 80) + ((lane >> 3) & 1) * 16);

    float acc[2][8][4];
#pragma unroll
    for (int a = 0; a < 2; a++)
#pragma unroll
        for (int b = 0; b < 8; b++)
#pragma unroll
            for (int c = 0; c < 4; c++) acc[a][b][c] = 0.f;

    issue(0);
    CPW0();
    __syncthreads();

#pragma unroll 1
    for (int c = 0; c < 8; c++) {
        if (c < 7) issue(c + 1);

        uint32_t st = sbase + (uint32_t)(c & 1) * 30720u;
        uint32_t AFw = st + AF + (uint32_t)(wm * 32) * 80u + aoff;
        uint32_t BHw = st + BH + (uint32_t)(wn * 64) * 80u + boff;
        uint32_t BLw = st + BL + (uint32_t)(wn * 64) * 80u + boff;
#pragma unroll
        for (int ks = 0; ks < 2; ks++) {
            uint32_t af[2][4];
#pragma unroll
            for (int mt = 0; mt < 2; mt++)
                ldmx4(af[mt], AFw + (uint32_t)(mt * 16) * 80u + ks * 32u);
            uint32_t bh[8][2];
#pragma unroll
            for (int p = 0; p < 4; p++) {
                uint32_t t4[4];
                ldmx4(t4, BHw + (uint32_t)(p * 16) * 80u + ks * 32u);
                bh[2 * p][0] = t4[0]; bh[2 * p][1] = t4[1];
                bh[2 * p + 1][0] = t4[2]; bh[2 * p + 1][1] = t4[3];
            }
#pragma unroll
            for (int mt = 0; mt < 2; mt++)
#pragma unroll
                for (int nt = 0; nt < 8; nt++)
                    mma16816h(acc[mt][nt], af[mt], bh[nt]);
            uint32_t bl[8][2];
#pragma unroll
            for (int p = 0; p < 4; p++) {
                uint32_t t4[4];
                ldmx4(t4, BLw + (uint32_t)(p * 16) * 80u + ks * 32u);
                bl[2 * p][0] = t4[0]; bl[2 * p][1] = t4[1];
                bl[2 * p + 1][0] = t4[2]; bl[2 * p + 1][1] = t4[3];
            }
#pragma unroll
            for (int mt = 0; mt < 2; mt++)
#pragma unroll
                for (int nt = 0; nt < 8; nt++)
                    mma16816h(acc[mt][nt], af[mt], bl[nt]);
        }
        if (c < 7) {
            CPW0();
            __syncthreads();
        }
    }

    int quad = lane >> 2, tg = lane & 3;
#pragma unroll
    for (int mt = 0; mt < 2; mt++) {
        int rbase = m0 + wm * 32 + mt * 16 + quad;
#pragma unroll
        for (int nt = 0; nt < 8; nt++) {
            int col = n0 + wn * 64 + nt * 8 + tg * 2;
            float2 bb = *(const float2*)(bias + col);
            if (mode == 0) {
                int sec = n0 >> 8;
                float sc = (sec == 0) ? QSCALE : 1.0f;
                int head = (col & 255) >> 5, dd = col & 31;
#pragma unroll
                for (int hf = 0; hf < 2; hf++) {
                    int rr = rbase + hf * 8;
                    int w = rr >> 9, nn = rr & 511;
                    size_t bxi = (size_t)(w * 8 + head);
                    size_t eoff = (bxi * 512 + nn) * 32 + dd;
                    float f0 = (acc[mt][nt][hf * 2 + 0] + bb.x) * sc;
                    float f1 = (acc[mt][nt][hf * 2 + 1] + bb.y) * sc;
                    if (sec == 0) {
                        *(uint32_t*)(g_qf + eoff) = pack_f16x2(f0, f1);
                    } else {
                        uint32_t hi, lo;
                        split2h(f0, f1, hi, lo);
                        *(uint32_t*)((sec == 1 ? g_kh : g_vh) + eoff) = hi;
                        *(uint32_t*)((sec == 1 ? g_kl : g_vl) + eoff) = lo;
                    }
                }
            } else {
#pragma unroll
                for (int hf = 0; hf < 2; hf++) {
                    int rr = rbase + hf * 8;
                    int off = g_tokoff[rr] + col;
                    float2 o;
                    o.x = acc[mt][nt][hf * 2 + 0] + bb.x;
                    o.y = acc[mt][nt][hf * 2 + 1] + bb.y;
                    *(float2*)(out + off) = o;
                }
            }
        }
    }
}

// ---------------------------------------------------------------------------
// HMMA attention (R16 shape): QK fp16 2-term; PV fp16 single-P 2-term.
// Epilogue writes single fp16 into g_acat for the proj GEMM.
// smem: Qf 10240 | 2 x (KH KL VH VL 5120 each = 20480). Total 51200 B.
// ---------------------------------------------------------------------------
__global__ void __launch_bounds__(256, 2) attn_mma_kernel() {
    extern __shared__ __align__(16) char sm[];
    uint32_t sb = smem_u32(sm);
    const int tid = threadIdx.x, lane = tid & 31, wid = tid >> 5;
    int bx = blockIdx.x >> 2, mtile = blockIdx.x & 3;
    int w = bx >> 3, h = bx & 7;
    int cfg = (((w >> 4) == 3) ? 4 : 0) | ((((w >> 2) & 3) == 3) ? 2 : 0) | (((w & 3) == 3) ? 1 : 0);

    const uint32_t SQF = 0, SBUF = 10240, BSTR = 20480;
    const uint32_t KH = 0, KL = 5120, VH = 10240, VL = 15360;

    int row_k = tid >> 2, seg_k = tid & 3;
    const char* kga = (const char*)g_kh + (size_t)bx * 32768 + row_k * 64 + seg_k * 16;
    const char* kgb = (const char*)g_kl + (size_t)bx * 32768 + row_k * 64 + seg_k * 16;
    const char* vga = (const char*)g_vh + (size_t)bx * 32768 + row_k * 64 + seg_k * 16;
    const char* vgb = (const char*)g_vl + (size_t)bx * 32768 + row_k * 64 + seg_k * 16;
    uint32_t kdst = row_k * 80 + seg_k * 16;

    auto issueKV = [&](int n) {
        uint32_t B2 = sb + SBUF + (uint32_t)(n & 1) * BSTR;
        CPA16(B2 + KH + kdst, kga + (size_t)n * 4096);
        CPA16(B2 + KL + kdst, kgb + (size_t)n * 4096);
        CPA16(B2 + VH + kdst, vga + (size_t)n * 4096);
        CPA16(B2 + VL + kdst, vgb + (size_t)n * 4096);
        CPC();
    };

    issueKV(0);

#pragma unroll
    for (int u = 0; u < 2; u++) {
        int lin = tid + u * 256;
        int row = lin >> 2, seg = lin & 3;
        size_t src = ((size_t)bx * 512 + mtile * 128 + row) * 32 + seg * 8;
        st128(sb + SQF + row * 80 + seg * 16, *(const uint4*)(g_qf + src));
    }
    CPW0();
    __syncthreads();

    uint32_t aoff = (uint32_t)(((lane & 7) + ((lane >> 3) & 1) * 8) * 80 + (lane >> 4) * 16);
    uint32_t boff = (uint32_t)(((lane & 7) + (lane >> 4) * 8) * 80 + ((lane >> 3) & 1) * 16);
    uint32_t qf[2][4];
#pragma unroll
    for (int ks = 0; ks < 2; ks++)
        ldmx4(qf[ks], sb + SQF + (uint32_t)(wid * 16) * 80 + aoff + ks * 32);

    float oacc[4][4];
#pragma unroll
    for (int a = 0; a < 4; a++)
#pragma unroll
        for (int b = 0; b < 4; b++) oacc[a][b] = 0.f;
    float rs0 = 0.f, rs1 = 0.f;
    int quad = lane >> 2, tg = lane & 3;
    int ib = mtile * 8 + wid;
    const __nv_bfloat16* bf = g_bfrag + ((((size_t)cfg * 8 + h) * 32 + ib) * 64) * 128;

#pragma unroll 1
    for (int jt = 0; jt < 8; jt++) {
        if (jt < 7) issueKV(jt + 1);
        uint32_t B = sb + SBUF + (uint32_t)(jt & 1) * BSTR;

        float sacc[8][4];
#pragma unroll
        for (int a = 0; a < 8; a++)
#pragma unroll
            for (int b = 0; b < 4; b++) sacc[a][b] = 0.f;
#pragma unroll
        for (int ks = 0; ks < 2; ks++)
#pragma unroll
            for (int p = 0; p < 4; p++) {
                uint32_t bh[4], bl[4];
                ldmx4(bh, B + KH + (uint32_t)(p * 16) * 80 + boff + ks * 32);
                ldmx4(bl, B + KL + (uint32_t)(p * 16) * 80 + boff + ks * 32);
#pragma unroll
                for (int n2 = 0; n2 < 2; n2++) {
                    mma16816h(sacc[2 * p + n2], qf[ks], &bh[n2 * 2]);
                    mma16816h(sacc[2 * p + n2], qf[ks], &bl[n2 * 2]);
                }
            }

        uint32_t aP[4][4];
#pragma unroll
        for (int nt = 0; nt < 8; nt++) {
            const uint32_t* bp = (const uint32_t*)(bf + (size_t)(jt * 8 + nt) * 128);
            __nv_bfloat162 bb01 = *(const __nv_bfloat162*)&bp[quad * 4 + tg];
            __nv_bfloat162 bb23 = *(const __nv_bfloat162*)&bp[32 + quad * 4 + tg];
            float2 b01 = __bfloat1622float2(bb01);
            float2 b23 = __bfloat1622float2(bb23);
            float p0 = exp2f(sacc[nt][0] + b01.x);
            float p1 = exp2f(sacc[nt][1] + b01.y);
            float p2 = exp2f(sacc[nt][2] + b23.x);
            float p3 = exp2f(sacc[nt][3] + b23.y);
            rs0 += p0 + p1;
            rs1 += p2 + p3;
            int kt = nt >> 1, o = (nt & 1) * 2;
            aP[kt][o]     = pack_f16x2(p0, p1);
            aP[kt][o + 1] = pack_f16x2(p2, p3);
        }

#pragma unroll
        for (int kt = 0; kt < 4; kt++) {
            uint32_t vh[4][2], vl[4][2];
#pragma unroll
            for (int dp = 0; dp < 2; dp++) {
                uint32_t t4[4];
                ldmx4t(t4, B + VH + (uint32_t)(kt * 16) * 80 + aoff + dp * 32);
                vh[dp * 2][0] = t4[0]; vh[dp * 2][1] = t4[1];
                vh[dp * 2 + 1][0] = t4[2]; vh[dp * 2 + 1][1] = t4[3];
                ldmx4t(t4, B + VL + (uint32_t)(kt * 16) * 80 + aoff + dp * 32);
                vl[dp * 2][0] = t4[0]; vl[dp * 2][1] = t4[1];
                vl[dp * 2 + 1][0] = t4[2]; vl[dp * 2 + 1][1] = t4[3];
            }
#pragma unroll
            for (int nb = 0; nb < 4; nb++) {
                mma16816h(oacc[nb], aP[kt], vh[nb]);
                mma16816h(oacc[nb], aP[kt], vl[nb]);
            }
        }

        if (jt < 7) {
            CPW0();
            __syncthreads();
        }
    }

    rs0 += __shfl_xor_sync(0xFFFFFFFF, rs0, 1);
    rs0 += __shfl_xor_sync(0xFFFFFFFF, rs0, 2);
    rs1 += __shfl_xor_sync(0xFFFFFFFF, rs1, 1);
    rs1 += __shfl_xor_sync(0xFFFFFFFF, rs1, 2);
    float inv0 = 1.f / rs0, inv1 = 1.f / rs1;
    int qtok = mtile * 128 + wid * 16 + quad;
    int t0 = w * 512 + qtok, t1 = t0 + 8;
#pragma unroll
    for (int nt = 0; nt < 4; nt++) {
        int c = h * 32 + nt * 8 + tg * 2;
        *(uint32_t*)(g_acat + (size_t)t0 * 256 + c) =
            pack_f16x2(oacc[nt][0] * inv0, oacc[nt][1] * inv0);
        *(uint32_t*)(g_acat + (size_t)t1 * 256 + c) =
            pack_f16x2(oacc[nt][2] * inv1, oacc[nt][3] * inv1);
    }
}

extern "C" void kernel_launch(void* const* d_in, const int* in_sizes, int n_in,
                              void* d_out, int out_size) {
    const float* x      = (const float*)d_in[0];
    const float* qkv_w  = (const float*)d_in[1];
    const float* qkv_b  = (const float*)d_in[2];
    const float* proj_w = (const float*)d_in[3];
    const float* proj_b = (const float*)d_in[4];
    const float* rpb    = (const float*)d_in[5];
    float* out = (float*)d_out;

    cudaFuncSetAttribute(hmma_gemm_kernel, cudaFuncAttributeMaxDynamicSharedMemorySize, 61440);
    cudaFuncSetAttribute(attn_mma_kernel, cudaFuncAttributeMaxDynamicSharedMemorySize, 51200);

    prep_tok_kernel<<<128, 256>>>();
    prep_bias_kernel<<<4096, 512>>>(rpb);
    conv_w_kernel<<<768, 32>>>(qkv_w);
    conv_a_kernel<<<4096, 256>>>(x);
    hmma_gemm_kernel<<<dim3(256, 6), 256, 61440>>>(qkv_b, nullptr, 0);
    conv_w_kernel<<<256, 32>>>(proj_w);
    attn_mma_kernel<<<2048, 256, 51200>>>();
    hmma_gemm_kernel<<<dim3(256, 2), 256, 61440>>>(proj_b, out, 1);
}